// round 1
// baseline (speedup 1.0000x reference)
#include <cuda_runtime.h>
#include <math.h>

// Problem constants
#define D_   1024
#define H_   16
#define DH_  64
#define B_   4
#define S_   2048
#define MTOK (B_ * S_)          // 8192 tokens
#define SCALE_ 0.125f           // DH^-0.5

// ---------------- scratch (device globals: no allocation allowed) ----------
__device__ float g_q [(size_t)B_ * H_ * S_ * DH_];   // [B,H,S,DH]
__device__ float g_k [(size_t)B_ * H_ * S_ * DH_];
__device__ float g_v [(size_t)B_ * H_ * S_ * DH_];
__device__ float g_ao[(size_t)MTOK * D_];            // [B,S,D] attention output

// ---------------- SGEMM tile config ----------------------------------------
#define BM 128
#define BN 128
#define BK 16
#define PA 132   // padded pitch for transposed A tile (reduces STS conflicts)

// ============================================================================
// Kernel 1: QKV projection.  C = x @ w_qkv + b_qkv, scattered into Q/K/V with
// head-major layout [B,H,S,DH]; Q scaled by SCALE_ in the epilogue.
// A: [8192,1024] row-major, B: [1024,3072] row-major.
// ============================================================================
__global__ __launch_bounds__(256) void qkv_gemm_kernel(
    const float* __restrict__ A,
    const float* __restrict__ Bw,
    const float* __restrict__ bias)
{
    __shared__ float As[BK * PA];   // transposed: As[k][m]
    __shared__ float Bs[BK * BN];   // Bs[k][n]

    const int tid = threadIdx.x;
    const int tx  = tid & 15;       // n dim
    const int ty  = tid >> 4;       // m dim
    const int row0 = blockIdx.y * BM;
    const int col0 = blockIdx.x * BN;
    const int N = 3 * D_;
    const int K = D_;

    float acc[8][8];
    #pragma unroll
    for (int i = 0; i < 8; i++)
        #pragma unroll
        for (int j = 0; j < 8; j++) acc[i][j] = 0.f;

    for (int k0 = 0; k0 < K; k0 += BK) {
        __syncthreads();
        #pragma unroll
        for (int p = 0; p < 2; p++) {
            int aidx = tid + p * 256;              // 0..511 float4s
            int arow = aidx >> 2;                  // 0..127
            int akk  = (aidx & 3) << 2;            // 0,4,8,12
            float4 a4 = *(const float4*)(A + (size_t)(row0 + arow) * K + k0 + akk);
            As[(akk + 0) * PA + arow] = a4.x;
            As[(akk + 1) * PA + arow] = a4.y;
            As[(akk + 2) * PA + arow] = a4.z;
            As[(akk + 3) * PA + arow] = a4.w;

            int bidx = tid + p * 256;
            int brow = bidx >> 5;                  // 0..15
            int bcol = (bidx & 31) << 2;           // 0..124
            *(float4*)(Bs + brow * BN + bcol) =
                *(const float4*)(Bw + (size_t)(k0 + brow) * N + col0 + bcol);
        }
        __syncthreads();

        #pragma unroll
        for (int kk = 0; kk < BK; kk++) {
            float af[8], bf[8];
            #pragma unroll
            for (int i = 0; i < 8; i++) af[i] = As[kk * PA + ty * 8 + i];
            float4 b0 = *(const float4*)(Bs + kk * BN + tx * 8);
            float4 b1 = *(const float4*)(Bs + kk * BN + tx * 8 + 4);
            bf[0]=b0.x; bf[1]=b0.y; bf[2]=b0.z; bf[3]=b0.w;
            bf[4]=b1.x; bf[5]=b1.y; bf[6]=b1.z; bf[7]=b1.w;
            #pragma unroll
            for (int i = 0; i < 8; i++)
                #pragma unroll
                for (int j = 0; j < 8; j++)
                    acc[i][j] = fmaf(af[i], bf[j], acc[i][j]);
        }
    }

    // Epilogue: bias + scatter to Q/K/V [B,H,S,DH]
    #pragma unroll
    for (int i = 0; i < 8; i++) {
        int gm = row0 + ty * 8 + i;     // token index
        int b  = gm >> 11;              // /2048
        int s  = gm & 2047;
        #pragma unroll
        for (int j = 0; j < 8; j++) {
            int gn = col0 + tx * 8 + j;
            float val = acc[i][j] + __ldg(bias + gn);
            int three = gn >> 10;                // which of q/k/v
            int h  = (gn >> 6) & 15;
            int dh = gn & 63;
            size_t dst = ((size_t)((b * H_ + h) * S_ + s)) * DH_ + dh;
            if (three == 0)      g_q[dst] = val * SCALE_;
            else if (three == 1) g_k[dst] = val;
            else                 g_v[dst] = val;
        }
    }
}

// ============================================================================
// Kernel 2: attention.  One block per (b,h, 64-query tile). Flash-style online
// softmax over 64 KV tiles of 32. Output to g_ao in [B,S,D] layout.
// ============================================================================
#define BR 64
#define BC 32
#define QP 65   // Qs pitch
#define KP 36   // Kt pitch (d-major, float4-aligned)
#define VP 68   // Vs pitch (float4-aligned)
#define SP 33   // Ssh pitch

__global__ __launch_bounds__(256) void attn_kernel()
{
    const int bh  = blockIdx.y;           // b*16 + h
    const int b   = bh >> 4;
    const int h   = bh & 15;
    const int qr0 = blockIdx.x * BR;
    const int t   = threadIdx.x;
    const int r   = t >> 2;               // query row within tile (0..63)
    const int cb  = t & 3;                // column block (0..3)

    __shared__ float Qs [BR * QP];        // [r][d]
    __shared__ float Kt [DH_ * KP];       // [d][c]  (transposed)
    __shared__ float Vs [BC * VP];        // [c][d]
    __shared__ float Ssh[BR * SP];        // [r][c]  probabilities

    const float* qbase = g_q + ((size_t)bh * S_ + qr0) * DH_;
    const float* kbase = g_k + (size_t)bh * S_ * DH_;
    const float* vbase = g_v + (size_t)bh * S_ * DH_;

    // Load Q tile (64 x 64)
    #pragma unroll
    for (int p = 0; p < 4; p++) {
        int idx = t + p * 256;            // 0..1023 float4s? no: 1024 f4 total/4
        int rr  = idx >> 4;               // 0..63
        int d0  = (idx & 15) << 2;        // 0..60
        float4 q4 = *(const float4*)(qbase + rr * DH_ + d0);
        Qs[rr * QP + d0 + 0] = q4.x;
        Qs[rr * QP + d0 + 1] = q4.y;
        Qs[rr * QP + d0 + 2] = q4.z;
        Qs[rr * QP + d0 + 3] = q4.w;
    }

    float m = -INFINITY, l = 0.f;
    float o[16];
    #pragma unroll
    for (int i = 0; i < 16; i++) o[i] = 0.f;

    const int c0 = cb * 8;                // this thread's 8 score columns
    const int d0 = cb * 16;               // this thread's 16 output dims

    for (int kc0 = 0; kc0 < S_; kc0 += BC) {
        __syncthreads();   // previous PV done before overwriting K/V tiles

        // Load K (transposed into Kt[d][c]) and V (Vs[c][d]); 32x64 each
        #pragma unroll
        for (int p = 0; p < 2; p++) {
            int idx = t + p * 256;        // 0..511 float4s
            int c   = idx >> 4;           // 0..31
            int dd  = (idx & 15) << 2;    // 0..60
            float4 k4 = *(const float4*)(kbase + (size_t)(kc0 + c) * DH_ + dd);
            Kt[(dd + 0) * KP + c] = k4.x;
            Kt[(dd + 1) * KP + c] = k4.y;
            Kt[(dd + 2) * KP + c] = k4.z;
            Kt[(dd + 3) * KP + c] = k4.w;
            float4 v4 = *(const float4*)(vbase + (size_t)(kc0 + c) * DH_ + dd);
            *(float4*)(Vs + c * VP + dd) = v4;
        }
        __syncthreads();

        // S = Q K^T for this thread's 8 columns
        float sc[8];
        #pragma unroll
        for (int j = 0; j < 8; j++) sc[j] = 0.f;
        #pragma unroll 8
        for (int d = 0; d < DH_; d++) {
            float q = Qs[r * QP + d];
            float4 k0 = *(const float4*)(Kt + d * KP + c0);
            float4 k1 = *(const float4*)(Kt + d * KP + c0 + 4);
            sc[0] = fmaf(q, k0.x, sc[0]);
            sc[1] = fmaf(q, k0.y, sc[1]);
            sc[2] = fmaf(q, k0.z, sc[2]);
            sc[3] = fmaf(q, k0.w, sc[3]);
            sc[4] = fmaf(q, k1.x, sc[4]);
            sc[5] = fmaf(q, k1.y, sc[5]);
            sc[6] = fmaf(q, k1.z, sc[6]);
            sc[7] = fmaf(q, k1.w, sc[7]);
        }

        // Row max across this thread's 8 + the 4 lanes of the row
        float mx = sc[0];
        #pragma unroll
        for (int j = 1; j < 8; j++) mx = fmaxf(mx, sc[j]);
        mx = fmaxf(mx, __shfl_xor_sync(0xffffffffu, mx, 1));
        mx = fmaxf(mx, __shfl_xor_sync(0xffffffffu, mx, 2));

        float mnew  = fmaxf(m, mx);
        float alpha = __expf(m - mnew);
        float rowsum = 0.f;
        #pragma unroll
        for (int j = 0; j < 8; j++) {
            sc[j] = __expf(sc[j] - mnew);
            rowsum += sc[j];
        }
        rowsum += __shfl_xor_sync(0xffffffffu, rowsum, 1);
        rowsum += __shfl_xor_sync(0xffffffffu, rowsum, 2);
        l = l * alpha + rowsum;
        m = mnew;
        #pragma unroll
        for (int i = 0; i < 16; i++) o[i] *= alpha;

        // Publish probabilities
        #pragma unroll
        for (int j = 0; j < 8; j++) Ssh[r * SP + c0 + j] = sc[j];
        __syncthreads();

        // O += P @ V   (thread owns row r, dims d0..d0+15)
        #pragma unroll 8
        for (int c = 0; c < BC; c++) {
            float p = Ssh[r * SP + c];
            const float* vrow = Vs + c * VP + d0;
            float4 v0 = *(const float4*)(vrow);
            float4 v1 = *(const float4*)(vrow + 4);
            float4 v2 = *(const float4*)(vrow + 8);
            float4 v3 = *(const float4*)(vrow + 12);
            o[ 0] = fmaf(p, v0.x, o[ 0]);  o[ 1] = fmaf(p, v0.y, o[ 1]);
            o[ 2] = fmaf(p, v0.z, o[ 2]);  o[ 3] = fmaf(p, v0.w, o[ 3]);
            o[ 4] = fmaf(p, v1.x, o[ 4]);  o[ 5] = fmaf(p, v1.y, o[ 5]);
            o[ 6] = fmaf(p, v1.z, o[ 6]);  o[ 7] = fmaf(p, v1.w, o[ 7]);
            o[ 8] = fmaf(p, v2.x, o[ 8]);  o[ 9] = fmaf(p, v2.y, o[ 9]);
            o[10] = fmaf(p, v2.z, o[10]);  o[11] = fmaf(p, v2.w, o[11]);
            o[12] = fmaf(p, v3.x, o[12]);  o[13] = fmaf(p, v3.y, o[13]);
            o[14] = fmaf(p, v3.z, o[14]);  o[15] = fmaf(p, v3.w, o[15]);
        }
    }

    // Epilogue: normalize and write [B,S,D] with D index = h*64 + d
    float inv = 1.0f / l;
    size_t obase = ((size_t)(b * S_ + qr0 + r)) * D_ + h * DH_ + d0;
    #pragma unroll
    for (int i = 0; i < 4; i++) {
        float4 w;
        w.x = o[i * 4 + 0] * inv;
        w.y = o[i * 4 + 1] * inv;
        w.z = o[i * 4 + 2] * inv;
        w.w = o[i * 4 + 3] * inv;
        *(float4*)(g_ao + obase + i * 4) = w;
    }
}

// ============================================================================
// Kernel 3: output projection.  out = g_ao @ w_out + b_out.  [8192,1024]x[1024,1024]
// ============================================================================
__global__ __launch_bounds__(256) void out_gemm_kernel(
    const float* __restrict__ Bw,
    const float* __restrict__ bias,
    float* __restrict__ out)
{
    __shared__ float As[BK * PA];
    __shared__ float Bs[BK * BN];

    const int tid = threadIdx.x;
    const int tx  = tid & 15;
    const int ty  = tid >> 4;
    const int row0 = blockIdx.y * BM;
    const int col0 = blockIdx.x * BN;
    const int N = D_;
    const int K = D_;
    const float* A = g_ao;

    float acc[8][8];
    #pragma unroll
    for (int i = 0; i < 8; i++)
        #pragma unroll
        for (int j = 0; j < 8; j++) acc[i][j] = 0.f;

    for (int k0 = 0; k0 < K; k0 += BK) {
        __syncthreads();
        #pragma unroll
        for (int p = 0; p < 2; p++) {
            int aidx = tid + p * 256;
            int arow = aidx >> 2;
            int akk  = (aidx & 3) << 2;
            float4 a4 = *(const float4*)(A + (size_t)(row0 + arow) * K + k0 + akk);
            As[(akk + 0) * PA + arow] = a4.x;
            As[(akk + 1) * PA + arow] = a4.y;
            As[(akk + 2) * PA + arow] = a4.z;
            As[(akk + 3) * PA + arow] = a4.w;

            int bidx = tid + p * 256;
            int brow = bidx >> 5;
            int bcol = (bidx & 31) << 2;
            *(float4*)(Bs + brow * BN + bcol) =
                *(const float4*)(Bw + (size_t)(k0 + brow) * N + col0 + bcol);
        }
        __syncthreads();

        #pragma unroll
        for (int kk = 0; kk < BK; kk++) {
            float af[8], bf[8];
            #pragma unroll
            for (int i = 0; i < 8; i++) af[i] = As[kk * PA + ty * 8 + i];
            float4 b0 = *(const float4*)(Bs + kk * BN + tx * 8);
            float4 b1 = *(const float4*)(Bs + kk * BN + tx * 8 + 4);
            bf[0]=b0.x; bf[1]=b0.y; bf[2]=b0.z; bf[3]=b0.w;
            bf[4]=b1.x; bf[5]=b1.y; bf[6]=b1.z; bf[7]=b1.w;
            #pragma unroll
            for (int i = 0; i < 8; i++)
                #pragma unroll
                for (int j = 0; j < 8; j++)
                    acc[i][j] = fmaf(af[i], bf[j], acc[i][j]);
        }
    }

    #pragma unroll
    for (int i = 0; i < 8; i++) {
        int gm = row0 + ty * 8 + i;
        #pragma unroll
        for (int j = 0; j < 8; j++) {
            int gn = col0 + tx * 8 + j;
            out[(size_t)gm * N + gn] = acc[i][j] + __ldg(bias + gn);
        }
    }
}

// ============================================================================
extern "C" void kernel_launch(void* const* d_in, const int* in_sizes, int n_in,
                              void* d_out, int out_size)
{
    const float* x     = (const float*)d_in[0];
    const float* w_qkv = (const float*)d_in[1];
    const float* b_qkv = (const float*)d_in[2];
    const float* w_out = (const float*)d_in[3];
    const float* b_out = (const float*)d_in[4];
    float* out = (float*)d_out;

    dim3 g1(3 * D_ / BN, MTOK / BM);   // (24, 64)
    qkv_gemm_kernel<<<g1, 256>>>(x, w_qkv, b_qkv);

    dim3 g2(S_ / BR, B_ * H_);         // (32, 64)
    attn_kernel<<<g2, 256>>>();

    dim3 g3(D_ / BN, MTOK / BM);       // (8, 64)
    out_gemm_kernel<<<g3, 256>>>(w_out, b_out, out);
}

// round 3
// speedup vs baseline: 2.1160x; 2.1160x over previous
#include <cuda_runtime.h>
#include <math.h>

// ---------------------------------------------------------------------------
// Problem constants
// ---------------------------------------------------------------------------
#define D_    1024
#define H_    16
#define DH_   64
#define B_    4
#define S_    2048
#define MTOK  (B_ * S_)
#define SCALE_ 0.125f

// ---------------------------------------------------------------------------
// Device-global scratch
// ---------------------------------------------------------------------------
__device__ float g_q     [(size_t)B_ * H_ * S_ * DH_];   // [B,H,S,DH], pre-scaled
__device__ float g_k     [(size_t)B_ * H_ * S_ * DH_];   // [B,H,S,DH]
__device__ float g_vT    [(size_t)B_ * H_ * DH_ * S_];   // [B,H,DH,S]
__device__ float g_scores[(size_t)B_ * H_ * S_ * S_];    // exp(scores), 1 GB
__device__ float g_spart [(size_t)B_ * H_ * S_ * 16];    // partial row sums
__device__ float g_ao    [(size_t)MTOK * D_];            // attention out [B,S,D]
__device__ float g_wqkvT [(size_t)3 * D_ * D_];          // w_qkv^T [3D, D]
__device__ float g_woutT [(size_t)D_ * D_];              // w_out^T [D, D]

// ---------------------------------------------------------------------------
// TF32 helpers
// ---------------------------------------------------------------------------
__device__ __forceinline__ unsigned f2tf32(float x) {
    unsigned r;
    asm("cvt.rna.tf32.f32 %0, %1;" : "=r"(r) : "f"(x));
    return r;
}

// m16n8k8 tf32 mma (sm_80+, valid on compute_103)
#define MMA8(c, a, b) asm volatile( \
    "mma.sync.aligned.m16n8k8.row.col.f32.tf32.tf32.f32 " \
    "{%0,%1,%2,%3}, {%4,%5,%6,%7}, {%8,%9}, {%0,%1,%2,%3};" \
    : "+f"((c)[0]), "+f"((c)[1]), "+f"((c)[2]), "+f"((c)[3]) \
    : "r"((a)[0]), "r"((a)[1]), "r"((a)[2]), "r"((a)[3]), \
      "r"((b)[0]), "r"((b)[1]))

// ---------------------------------------------------------------------------
// GEMM mainloop: C[128 x BN] = A[128 x K] @ B[BN x K]^T  (both K-major).
// 8 warps; BN=128 -> warps 2x4 (warp tile 64x32); BN=64 -> 4x2 (32x32).
// SMEM staged in mma-fragment order:
//   A: frag[(mt*4+kt)][reg 0..3][lane 0..31]   (owner lane = (r%8)*4 + c%4,
//      reg = r/8 + 2*(c/4))  -> producer STS.128, consumer conflict-free LDS
//   B: frag[(nt*4+kt)][reg 0..1][lane]         (owner lane = n*4 + k%4,
//      reg = k/4)
// TX=true: 3xTF32 (hi/lo split) for ~fp32 accuracy.
// Result left in dsm as Cstage[128][BN+4] floats; returns after syncthreads.
// ---------------------------------------------------------------------------
template <int BN, bool TX>
__device__ __forceinline__ void gemm_tile(
    const float* __restrict__ A, int lda,
    const float* __restrict__ Bm, int ldb,
    int K, float* __restrict__ dsm)
{
    constexpr int BNK    = BN * 32;                    // B tile floats
    constexpr int STAGE  = (4096 + BNK) * (TX ? 2 : 1);
    constexpr int OFF_B  = 4096;
    constexpr int OFF_AL = 4096 + BNK;                 // A-lo (TX)
    constexpr int OFF_BL = 8192 + BNK;                 // B-lo (TX)
    constexpr int WN     = BN / 32;
    constexpr int WM     = 8 / WN;
    constexpr int MTL    = 8 / WM;                     // m16-tiles per warp
    constexpr int NB4    = BNK / 1024;                 // B float4 loads/thread
    constexpr int PITCH  = BN + 4;

    const int tid  = threadIdx.x;
    const int lane = tid & 31;
    const int wid  = tid >> 5;
    const int wm   = wid / WN;
    const int wn   = wid % WN;

    float c[MTL][4][4];
    #pragma unroll
    for (int m = 0; m < MTL; ++m)
        #pragma unroll
        for (int n = 0; n < 4; ++n)
            #pragma unroll
            for (int r = 0; r < 4; ++r) c[m][n][r] = 0.f;

    float4 ra[4], rb[NB4];

    auto gload = [&](int k0) {
        #pragma unroll
        for (int p = 0; p < 4; ++p) {
            int idx = tid + (p << 8);
            ra[p] = *(const float4*)(A + (size_t)(idx >> 3) * lda + k0 + ((idx & 7) << 2));
        }
        #pragma unroll
        for (int p = 0; p < NB4; ++p) {
            int idx = tid + (p << 8);
            rb[p] = *(const float4*)(Bm + (size_t)(idx >> 3) * ldb + k0 + ((idx & 7) << 2));
        }
    };

    auto stage_sts = [&](int s) {
        float* st = dsm + (s & 1) * STAGE;
        #pragma unroll
        for (int p = 0; p < 4; ++p) {
            int idx = tid + (p << 8);
            int row = idx >> 3, kk = (idx & 7) << 2;
            int f    = (row >> 4) * 4 + (kk >> 3);
            int reg  = ((row >> 3) & 1) + (((kk >> 2) & 1) << 1);
            int addr = (f * 4 + reg) * 32 + (row & 7) * 4;
            float4 v = ra[p];
            uint4 h;
            h.x = f2tf32(v.x); h.y = f2tf32(v.y); h.z = f2tf32(v.z); h.w = f2tf32(v.w);
            *(uint4*)(st + addr) = h;
            if (TX) {
                float4 l4;
                l4.x = v.x - __uint_as_float(h.x);
                l4.y = v.y - __uint_as_float(h.y);
                l4.z = v.z - __uint_as_float(h.z);
                l4.w = v.w - __uint_as_float(h.w);
                uint4 l;
                l.x = f2tf32(l4.x); l.y = f2tf32(l4.y);
                l.z = f2tf32(l4.z); l.w = f2tf32(l4.w);
                *(uint4*)(st + OFF_AL + addr) = l;
            }
        }
        #pragma unroll
        for (int p = 0; p < NB4; ++p) {
            int idx = tid + (p << 8);
            int row = idx >> 3, kk = (idx & 7) << 2;
            int fb   = ((row >> 3) * 4 + (kk >> 3)) * 2 + ((kk >> 2) & 1);
            int addr = fb * 32 + (row & 7) * 4;
            float4 v = rb[p];
            uint4 h;
            h.x = f2tf32(v.x); h.y = f2tf32(v.y); h.z = f2tf32(v.z); h.w = f2tf32(v.w);
            *(uint4*)(st + OFF_B + addr) = h;
            if (TX) {
                float4 l4;
                l4.x = v.x - __uint_as_float(h.x);
                l4.y = v.y - __uint_as_float(h.y);
                l4.z = v.z - __uint_as_float(h.z);
                l4.w = v.w - __uint_as_float(h.w);
                uint4 l;
                l.x = f2tf32(l4.x); l.y = f2tf32(l4.y);
                l.z = f2tf32(l4.z); l.w = f2tf32(l4.w);
                *(uint4*)(st + OFF_BL + addr) = l;
            }
        }
    };

    const int nch = K >> 5;
    gload(0);
    stage_sts(0);
    __syncthreads();

    for (int s = 0; s < nch; ++s) {
        if (s + 1 < nch) gload((s + 1) << 5);
        const float* st = dsm + (s & 1) * STAGE;
        #pragma unroll
        for (int kt = 0; kt < 4; ++kt) {
            unsigned ah[MTL][4], al[MTL][4], bh[4][2], bl[4][2];
            #pragma unroll
            for (int m = 0; m < MTL; ++m) {
                int f = (((wm * MTL + m) * 4 + kt) * 4) * 32 + lane;
                #pragma unroll
                for (int r = 0; r < 4; ++r) {
                    ah[m][r] = __float_as_uint(st[f + r * 32]);
                    if (TX) al[m][r] = __float_as_uint(st[OFF_AL + f + r * 32]);
                }
            }
            #pragma unroll
            for (int n = 0; n < 4; ++n) {
                int fb = (((wn * 4 + n) * 4 + kt) * 2) * 32 + lane;
                bh[n][0] = __float_as_uint(st[OFF_B + fb]);
                bh[n][1] = __float_as_uint(st[OFF_B + fb + 32]);
                if (TX) {
                    bl[n][0] = __float_as_uint(st[OFF_BL + fb]);
                    bl[n][1] = __float_as_uint(st[OFF_BL + fb + 32]);
                }
            }
            #pragma unroll
            for (int m = 0; m < MTL; ++m)
                #pragma unroll
                for (int n = 0; n < 4; ++n) {
                    MMA8(c[m][n], ah[m], bh[n]);
                    if (TX) {
                        MMA8(c[m][n], ah[m], bl[n]);
                        MMA8(c[m][n], al[m], bh[n]);
                    }
                }
        }
        __syncthreads();
        if (s + 1 < nch) { stage_sts(s + 1); __syncthreads(); }
    }

    // C fragments -> Cstage[128][PITCH]
    const int g = lane >> 2, tig = lane & 3;
    #pragma unroll
    for (int m = 0; m < MTL; ++m)
        #pragma unroll
        for (int n = 0; n < 4; ++n) {
            int row = wm * (MTL * 16) + m * 16 + g;
            int col = wn * 32 + n * 8 + tig * 2;
            *(float2*)(dsm + row * PITCH + col)       = make_float2(c[m][n][0], c[m][n][1]);
            *(float2*)(dsm + (row + 8) * PITCH + col) = make_float2(c[m][n][2], c[m][n][3]);
        }
    __syncthreads();
}

// Dynamic smem sizes (bytes)
#define DYN_3X  131584    // 2 stages * (A+B hi+lo) = 131072 + aux 512
#define DYN_OUT 67584     // Cstage 128*132*4 dominates
#define DYN_PV  49152     // 2 stages * (4096+2048)*4

// ---------------------------------------------------------------------------
// Kernel 0: weight transpose
// ---------------------------------------------------------------------------
__global__ __launch_bounds__(256) void k_transpose(
    const float* __restrict__ in, int rows, int cols, int which)
{
    __shared__ float tile[32][33];
    float* outp = which ? g_woutT : g_wqkvT;
    int bx = blockIdx.x * 32, by = blockIdx.y * 32;
    int tx = threadIdx.x, ty = threadIdx.y;
    #pragma unroll
    for (int i = 0; i < 32; i += 8)
        tile[ty + i][tx] = in[(size_t)(by + ty + i) * cols + bx + tx];
    __syncthreads();
    #pragma unroll
    for (int i = 0; i < 32; i += 8)
        outp[(size_t)(bx + ty + i) * rows + by + tx] = tile[tx][ty + i];
}

// ---------------------------------------------------------------------------
// Kernel 1: QKV projection (3xTF32) -> scatter into g_q / g_k / g_vT
// ---------------------------------------------------------------------------
__global__ __launch_bounds__(256) void k_gemm_qkv(
    const float* __restrict__ x, const float* __restrict__ bias)
{
    extern __shared__ __align__(16) float dsm[];
    const float* A  = x + (size_t)blockIdx.y * 128 * D_;
    const float* Bm = g_wqkvT + (size_t)blockIdx.x * 128 * D_;
    gemm_tile<128, true>(A, D_, Bm, D_, D_, dsm);

    const int tid = threadIdx.x, lane = tid & 31, wid = tid >> 5;
    const int sub = wid & 3, half = wid >> 2;
    const int rowl = sub * 32 + lane;

    float vals[64];
    const float* crow = dsm + rowl * 132 + half * 64;
    const int gn0 = blockIdx.x * 128 + half * 64;
    #pragma unroll
    for (int j = 0; j < 64; j += 4) {
        float4 f = *(const float4*)(crow + j);
        vals[j]   = f.x + __ldg(bias + gn0 + j);
        vals[j+1] = f.y + __ldg(bias + gn0 + j + 1);
        vals[j+2] = f.z + __ldg(bias + gn0 + j + 2);
        vals[j+3] = f.w + __ldg(bias + gn0 + j + 3);
    }

    const int gm = blockIdx.y * 128 + rowl;
    const int b  = gm >> 11, s = gm & 2047;
    const int bx = blockIdx.x;
    const int three = bx >> 3;
    const int h = ((bx & 7) << 1) + half;

    if (three == 0) {
        float* dst = g_q + (((size_t)(b * H_ + h) * S_ + s) << 6);
        #pragma unroll
        for (int j = 0; j < 64; j += 4) {
            float4 o = {vals[j] * SCALE_, vals[j+1] * SCALE_,
                        vals[j+2] * SCALE_, vals[j+3] * SCALE_};
            *(float4*)(dst + j) = o;
        }
    } else if (three == 1) {
        float* dst = g_k + (((size_t)(b * H_ + h) * S_ + s) << 6);
        #pragma unroll
        for (int j = 0; j < 64; j += 4) {
            float4 o = {vals[j], vals[j+1], vals[j+2], vals[j+3]};
            *(float4*)(dst + j) = o;
        }
    } else {
        float* base = g_vT + ((size_t)(b * H_ + h) << 6) * S_ + s;
        #pragma unroll
        for (int j = 0; j < 64; ++j)
            base[(size_t)j * S_] = vals[j];
    }
}

// ---------------------------------------------------------------------------
// Kernel 2: scores = exp(Q K^T) (3xTF32) -> g_scores + partial row sums
// ---------------------------------------------------------------------------
__global__ __launch_bounds__(256) void k_gemm_scores()
{
    extern __shared__ __align__(16) float dsm[];
    const int bh = blockIdx.z;
    const float* A  = g_q + ((size_t)bh * S_ + blockIdx.y * 128) * DH_;
    const float* Bm = g_k + ((size_t)bh * S_ + blockIdx.x * 128) * DH_;
    gemm_tile<128, true>(A, DH_, Bm, DH_, DH_, dsm);

    const int tid = threadIdx.x, lane = tid & 31, wid = tid >> 5;
    const int sub = wid & 3, half = wid >> 2;
    const int rowl = sub * 32 + lane;

    float* crow = dsm + rowl * 132 + half * 64;
    float sum = 0.f;
    #pragma unroll
    for (int j = 0; j < 64; j += 4) {
        float4 f = *(const float4*)(crow + j);
        f.x = __expf(f.x); f.y = __expf(f.y);
        f.z = __expf(f.z); f.w = __expf(f.w);
        sum += f.x + f.y + f.z + f.w;
        *(float4*)(crow + j) = f;
    }

    float* rsum = dsm + 32768;  // aux region past the 3x stage buffers
    if (half == 0) rsum[rowl] = sum;
    __syncthreads();
    if (half == 1)
        g_spart[((size_t)bh * S_ + blockIdx.y * 128 + rowl) * 16 + blockIdx.x]
            = rsum[rowl] + sum;

    // Coalesced copy Cstage -> g_scores
    float* orow = g_scores + ((size_t)bh * S_ + blockIdx.y * 128) * S_
                + blockIdx.x * 128;
    for (int r = wid; r < 128; r += 8) {
        float4 f = *(const float4*)(dsm + r * 132 + lane * 4);
        *(float4*)(orow + (size_t)r * S_ + lane * 4) = f;
    }
}

// ---------------------------------------------------------------------------
// Kernel 3: PV (1xTF32): (P @ V) / rowsum -> g_ao
// ---------------------------------------------------------------------------
__global__ __launch_bounds__(256) void k_gemm_pv()
{
    extern __shared__ __align__(16) float dsm[];
    const int bh = blockIdx.z;
    const int row0 = blockIdx.y * 128;
    const float* A  = g_scores + ((size_t)bh * S_ + row0) * S_;
    const float* Bm = g_vT + (size_t)bh * DH_ * S_;
    gemm_tile<64, false>(A, S_, Bm, S_, S_, dsm);

    const int tid = threadIdx.x, lane = tid & 31, wid = tid >> 5;
    const int sub = wid & 3, half = wid >> 2;
    const int rowl = sub * 32 + lane;
    const int qrow = row0 + rowl;

    const float* sp = g_spart + ((size_t)bh * S_ + qrow) * 16;
    float tot = 0.f;
    #pragma unroll
    for (int i = 0; i < 16; ++i) tot += __ldg(sp + i);
    const float inv = 1.0f / tot;

    const int b = bh >> 4, h = bh & 15;
    const float* crow = dsm + rowl * 68 + half * 32;
    float* dst = g_ao + (size_t)(b * S_ + qrow) * D_ + h * 64 + half * 32;
    #pragma unroll
    for (int j = 0; j < 32; j += 4) {
        float4 f = *(const float4*)(crow + j);
        float4 o = {f.x * inv, f.y * inv, f.z * inv, f.w * inv};
        *(float4*)(dst + j) = o;
    }
}

// ---------------------------------------------------------------------------
// Kernel 4: output projection (1xTF32)
// ---------------------------------------------------------------------------
__global__ __launch_bounds__(256) void k_gemm_out(
    const float* __restrict__ bias, float* __restrict__ out)
{
    extern __shared__ __align__(16) float dsm[];
    const float* A  = g_ao + (size_t)blockIdx.y * 128 * D_;
    const float* Bm = g_woutT + (size_t)blockIdx.x * 128 * D_;
    gemm_tile<128, false>(A, D_, Bm, D_, D_, dsm);

    const int tid = threadIdx.x, lane = tid & 31, wid = tid >> 5;
    const int sub = wid & 3, half = wid >> 2;
    const int rowl = sub * 32 + lane;

    const float* crow = dsm + rowl * 132 + half * 64;
    const int gm  = blockIdx.y * 128 + rowl;
    const int gn0 = blockIdx.x * 128 + half * 64;
    float* dst = out + (size_t)gm * D_ + gn0;
    #pragma unroll
    for (int j = 0; j < 64; j += 4) {
        float4 f = *(const float4*)(crow + j);
        float4 o = {f.x + __ldg(bias + gn0 + j),
                    f.y + __ldg(bias + gn0 + j + 1),
                    f.z + __ldg(bias + gn0 + j + 2),
                    f.w + __ldg(bias + gn0 + j + 3)};
        *(float4*)(dst + j) = o;
    }
}

// ---------------------------------------------------------------------------
extern "C" void kernel_launch(void* const* d_in, const int* in_sizes, int n_in,
                              void* d_out, int out_size)
{
    (void)in_sizes; (void)n_in; (void)out_size;
    const float* x     = (const float*)d_in[0];
    const float* w_qkv = (const float*)d_in[1];
    const float* b_qkv = (const float*)d_in[2];
    const float* w_out = (const float*)d_in[3];
    const float* b_out = (const float*)d_in[4];
    float* out = (float*)d_out;

    cudaFuncSetAttribute(k_gemm_qkv,    cudaFuncAttributeMaxDynamicSharedMemorySize, DYN_3X);
    cudaFuncSetAttribute(k_gemm_scores, cudaFuncAttributeMaxDynamicSharedMemorySize, DYN_3X);
    cudaFuncSetAttribute(k_gemm_pv,     cudaFuncAttributeMaxDynamicSharedMemorySize, DYN_PV);
    cudaFuncSetAttribute(k_gemm_out,    cudaFuncAttributeMaxDynamicSharedMemorySize, DYN_OUT);

    k_transpose<<<dim3(96, 32), dim3(32, 8)>>>(w_qkv, D_, 3 * D_, 0);
    k_transpose<<<dim3(32, 32), dim3(32, 8)>>>(w_out, D_, D_, 1);

    k_gemm_qkv<<<dim3(24, 64), 256, DYN_3X>>>(x, b_qkv);
    k_gemm_scores<<<dim3(16, 16, 64), 256, DYN_3X>>>();
    k_gemm_pv<<<dim3(1, 16, 64), 256, DYN_PV>>>();
    k_gemm_out<<<dim3(8, 64), 256, DYN_OUT>>>(b_out, out);
}

// round 4
// speedup vs baseline: 2.1184x; 1.0011x over previous
#include <cuda_runtime.h>
#include <math.h>

// ---------------------------------------------------------------------------
// Problem constants
// ---------------------------------------------------------------------------
#define D_    1024
#define H_    16
#define DH_   64
#define B_    4
#define S_    2048
#define MTOK  (B_ * S_)
#define SCALE_ 0.125f

// ---------------------------------------------------------------------------
// Device-global scratch
// ---------------------------------------------------------------------------
__device__ float g_q     [(size_t)B_ * H_ * S_ * DH_];   // [B,H,S,DH], pre-scaled
__device__ float g_k     [(size_t)B_ * H_ * S_ * DH_];   // [B,H,S,DH]
__device__ float g_vT    [(size_t)B_ * H_ * DH_ * S_];   // [B,H,DH,S]
__device__ float g_scores[(size_t)B_ * H_ * S_ * S_];    // exp(scores), 1 GB
__device__ float g_spart [(size_t)B_ * H_ * S_ * 16];    // partial row sums
__device__ float g_ao    [(size_t)MTOK * D_];            // attention out [B,S,D]
__device__ float g_wqkvT [(size_t)3 * D_ * D_];          // w_qkv^T [3D, D]
__device__ float g_woutT [(size_t)D_ * D_];              // w_out^T [D, D]

// ---------------------------------------------------------------------------
// TF32 helpers
// ---------------------------------------------------------------------------
__device__ __forceinline__ unsigned f2tf32(float x) {
    unsigned r;
    asm("cvt.rna.tf32.f32 %0, %1;" : "=r"(r) : "f"(x));
    return r;
}

// m16n8k8 tf32 mma (sm_80+, valid on compute_103)
#define MMA8(c, a, b) asm volatile( \
    "mma.sync.aligned.m16n8k8.row.col.f32.tf32.tf32.f32 " \
    "{%0,%1,%2,%3}, {%4,%5,%6,%7}, {%8,%9}, {%0,%1,%2,%3};" \
    : "+f"((c)[0]), "+f"((c)[1]), "+f"((c)[2]), "+f"((c)[3]) \
    : "r"((a)[0]), "r"((a)[1]), "r"((a)[2]), "r"((a)[3]), \
      "r"((b)[0]), "r"((b)[1]))

// ---------------------------------------------------------------------------
// GEMM mainloop: C[128 x BN] = A[128 x K] @ B[BN x K]^T  (both K-major).
// 8 warps; BN=128 -> warps 2x4 (warp tile 64x32); BN=64 -> 4x2 (32x32).
// SMEM staged in mma-fragment order:
//   A: frag[(mt*4+kt)][reg 0..3][lane 0..31]   (owner lane = (r%8)*4 + c%4,
//      reg = r/8 + 2*(c/4))  -> producer STS.128, consumer conflict-free LDS
//   B: frag[(nt*4+kt)][reg 0..1][lane]         (owner lane = n*4 + k%4,
//      reg = k/4)
// TX=true: 3xTF32 (hi/lo split) for ~fp32 accuracy.
// Result left in dsm as Cstage[128][BN+4] floats; returns after syncthreads.
// ---------------------------------------------------------------------------
template <int BN, bool TX>
__device__ __forceinline__ void gemm_tile(
    const float* __restrict__ A, int lda,
    const float* __restrict__ Bm, int ldb,
    int K, float* __restrict__ dsm)
{
    constexpr int BNK    = BN * 32;                    // B tile floats
    constexpr int STAGE  = (4096 + BNK) * (TX ? 2 : 1);
    constexpr int OFF_B  = 4096;
    constexpr int OFF_AL = 4096 + BNK;                 // A-lo (TX)
    constexpr int OFF_BL = 8192 + BNK;                 // B-lo (TX)
    constexpr int WN     = BN / 32;
    constexpr int WM     = 8 / WN;
    constexpr int MTL    = 8 / WM;                     // m16-tiles per warp
    constexpr int NB4    = BNK / 1024;                 // B float4 loads/thread
    constexpr int PITCH  = BN + 4;

    const int tid  = threadIdx.x;
    const int lane = tid & 31;
    const int wid  = tid >> 5;
    const int wm   = wid / WN;
    const int wn   = wid % WN;

    float c[MTL][4][4];
    #pragma unroll
    for (int m = 0; m < MTL; ++m)
        #pragma unroll
        for (int n = 0; n < 4; ++n)
            #pragma unroll
            for (int r = 0; r < 4; ++r) c[m][n][r] = 0.f;

    float4 ra[4], rb[NB4];

    auto gload = [&](int k0) {
        #pragma unroll
        for (int p = 0; p < 4; ++p) {
            int idx = tid + (p << 8);
            ra[p] = *(const float4*)(A + (size_t)(idx >> 3) * lda + k0 + ((idx & 7) << 2));
        }
        #pragma unroll
        for (int p = 0; p < NB4; ++p) {
            int idx = tid + (p << 8);
            rb[p] = *(const float4*)(Bm + (size_t)(idx >> 3) * ldb + k0 + ((idx & 7) << 2));
        }
    };

    auto stage_sts = [&](int s) {
        float* st = dsm + (s & 1) * STAGE;
        #pragma unroll
        for (int p = 0; p < 4; ++p) {
            int idx = tid + (p << 8);
            int row = idx >> 3, kk = (idx & 7) << 2;
            int f    = (row >> 4) * 4 + (kk >> 3);
            int reg  = ((row >> 3) & 1) + (((kk >> 2) & 1) << 1);
            int addr = (f * 4 + reg) * 32 + (row & 7) * 4;
            float4 v = ra[p];
            uint4 h;
            h.x = f2tf32(v.x); h.y = f2tf32(v.y); h.z = f2tf32(v.z); h.w = f2tf32(v.w);
            *(uint4*)(st + addr) = h;
            if (TX) {
                float4 l4;
                l4.x = v.x - __uint_as_float(h.x);
                l4.y = v.y - __uint_as_float(h.y);
                l4.z = v.z - __uint_as_float(h.z);
                l4.w = v.w - __uint_as_float(h.w);
                uint4 l;
                l.x = f2tf32(l4.x); l.y = f2tf32(l4.y);
                l.z = f2tf32(l4.z); l.w = f2tf32(l4.w);
                *(uint4*)(st + OFF_AL + addr) = l;
            }
        }
        #pragma unroll
        for (int p = 0; p < NB4; ++p) {
            int idx = tid + (p << 8);
            int row = idx >> 3, kk = (idx & 7) << 2;
            int fb   = ((row >> 3) * 4 + (kk >> 3)) * 2 + ((kk >> 2) & 1);
            int addr = fb * 32 + (row & 7) * 4;
            float4 v = rb[p];
            uint4 h;
            h.x = f2tf32(v.x); h.y = f2tf32(v.y); h.z = f2tf32(v.z); h.w = f2tf32(v.w);
            *(uint4*)(st + OFF_B + addr) = h;
            if (TX) {
                float4 l4;
                l4.x = v.x - __uint_as_float(h.x);
                l4.y = v.y - __uint_as_float(h.y);
                l4.z = v.z - __uint_as_float(h.z);
                l4.w = v.w - __uint_as_float(h.w);
                uint4 l;
                l.x = f2tf32(l4.x); l.y = f2tf32(l4.y);
                l.z = f2tf32(l4.z); l.w = f2tf32(l4.w);
                *(uint4*)(st + OFF_BL + addr) = l;
            }
        }
    };

    const int nch = K >> 5;
    gload(0);
    stage_sts(0);
    __syncthreads();

    for (int s = 0; s < nch; ++s) {
        if (s + 1 < nch) gload((s + 1) << 5);
        const float* st = dsm + (s & 1) * STAGE;
        #pragma unroll
        for (int kt = 0; kt < 4; ++kt) {
            unsigned ah[MTL][4], al[MTL][4], bh[4][2], bl[4][2];
            #pragma unroll
            for (int m = 0; m < MTL; ++m) {
                int f = (((wm * MTL + m) * 4 + kt) * 4) * 32 + lane;
                #pragma unroll
                for (int r = 0; r < 4; ++r) {
                    ah[m][r] = __float_as_uint(st[f + r * 32]);
                    if (TX) al[m][r] = __float_as_uint(st[OFF_AL + f + r * 32]);
                }
            }
            #pragma unroll
            for (int n = 0; n < 4; ++n) {
                int fb = (((wn * 4 + n) * 4 + kt) * 2) * 32 + lane;
                bh[n][0] = __float_as_uint(st[OFF_B + fb]);
                bh[n][1] = __float_as_uint(st[OFF_B + fb + 32]);
                if (TX) {
                    bl[n][0] = __float_as_uint(st[OFF_BL + fb]);
                    bl[n][1] = __float_as_uint(st[OFF_BL + fb + 32]);
                }
            }
            #pragma unroll
            for (int m = 0; m < MTL; ++m)
                #pragma unroll
                for (int n = 0; n < 4; ++n) {
                    MMA8(c[m][n], ah[m], bh[n]);
                    if (TX) {
                        MMA8(c[m][n], ah[m], bl[n]);
                        MMA8(c[m][n], al[m], bh[n]);
                    }
                }
        }
        __syncthreads();
        if (s + 1 < nch) { stage_sts(s + 1); __syncthreads(); }
    }

    // C fragments -> Cstage[128][PITCH]
    const int g = lane >> 2, tig = lane & 3;
    #pragma unroll
    for (int m = 0; m < MTL; ++m)
        #pragma unroll
        for (int n = 0; n < 4; ++n) {
            int row = wm * (MTL * 16) + m * 16 + g;
            int col = wn * 32 + n * 8 + tig * 2;
            *(float2*)(dsm + row * PITCH + col)       = make_float2(c[m][n][0], c[m][n][1]);
            *(float2*)(dsm + (row + 8) * PITCH + col) = make_float2(c[m][n][2], c[m][n][3]);
        }
    __syncthreads();
}

// Dynamic smem sizes (bytes)
#define DYN_3X  131584    // 2 stages * (A+B hi+lo) = 131072 + aux 512
#define DYN_OUT 67584     // Cstage 128*132*4 dominates
#define DYN_PV  49152     // 2 stages * (4096+2048)*4

// ---------------------------------------------------------------------------
// Kernel 0: weight transpose
// ---------------------------------------------------------------------------
__global__ __launch_bounds__(256) void k_transpose(
    const float* __restrict__ in, int rows, int cols, int which)
{
    __shared__ float tile[32][33];
    float* outp = which ? g_woutT : g_wqkvT;
    int bx = blockIdx.x * 32, by = blockIdx.y * 32;
    int tx = threadIdx.x, ty = threadIdx.y;
    #pragma unroll
    for (int i = 0; i < 32; i += 8)
        tile[ty + i][tx] = in[(size_t)(by + ty + i) * cols + bx + tx];
    __syncthreads();
    #pragma unroll
    for (int i = 0; i < 32; i += 8)
        outp[(size_t)(bx + ty + i) * rows + by + tx] = tile[tx][ty + i];
}

// ---------------------------------------------------------------------------
// Kernel 1: QKV projection (3xTF32) -> scatter into g_q / g_k / g_vT
// ---------------------------------------------------------------------------
__global__ __launch_bounds__(256) void k_gemm_qkv(
    const float* __restrict__ x, const float* __restrict__ bias)
{
    extern __shared__ __align__(16) float dsm[];
    const float* A  = x + (size_t)blockIdx.y * 128 * D_;
    const float* Bm = g_wqkvT + (size_t)blockIdx.x * 128 * D_;
    gemm_tile<128, true>(A, D_, Bm, D_, D_, dsm);

    const int tid = threadIdx.x, lane = tid & 31, wid = tid >> 5;
    const int sub = wid & 3, half = wid >> 2;
    const int rowl = sub * 32 + lane;

    float vals[64];
    const float* crow = dsm + rowl * 132 + half * 64;
    const int gn0 = blockIdx.x * 128 + half * 64;
    #pragma unroll
    for (int j = 0; j < 64; j += 4) {
        float4 f = *(const float4*)(crow + j);
        vals[j]   = f.x + __ldg(bias + gn0 + j);
        vals[j+1] = f.y + __ldg(bias + gn0 + j + 1);
        vals[j+2] = f.z + __ldg(bias + gn0 + j + 2);
        vals[j+3] = f.w + __ldg(bias + gn0 + j + 3);
    }

    const int gm = blockIdx.y * 128 + rowl;
    const int b  = gm >> 11, s = gm & 2047;
    const int bx = blockIdx.x;
    const int three = bx >> 3;
    const int h = ((bx & 7) << 1) + half;

    if (three == 0) {
        float* dst = g_q + (((size_t)(b * H_ + h) * S_ + s) << 6);
        #pragma unroll
        for (int j = 0; j < 64; j += 4) {
            float4 o = {vals[j] * SCALE_, vals[j+1] * SCALE_,
                        vals[j+2] * SCALE_, vals[j+3] * SCALE_};
            *(float4*)(dst + j) = o;
        }
    } else if (three == 1) {
        float* dst = g_k + (((size_t)(b * H_ + h) * S_ + s) << 6);
        #pragma unroll
        for (int j = 0; j < 64; j += 4) {
            float4 o = {vals[j], vals[j+1], vals[j+2], vals[j+3]};
            *(float4*)(dst + j) = o;
        }
    } else {
        float* base = g_vT + ((size_t)(b * H_ + h) << 6) * S_ + s;
        #pragma unroll
        for (int j = 0; j < 64; ++j)
            base[(size_t)j * S_] = vals[j];
    }
}

// ---------------------------------------------------------------------------
// Kernel 2: scores = exp(Q K^T) (3xTF32) -> g_scores + partial row sums
// ---------------------------------------------------------------------------
__global__ __launch_bounds__(256) void k_gemm_scores()
{
    extern __shared__ __align__(16) float dsm[];
    const int bh = blockIdx.z;
    const float* A  = g_q + ((size_t)bh * S_ + blockIdx.y * 128) * DH_;
    const float* Bm = g_k + ((size_t)bh * S_ + blockIdx.x * 128) * DH_;
    gemm_tile<128, true>(A, DH_, Bm, DH_, DH_, dsm);

    const int tid = threadIdx.x, lane = tid & 31, wid = tid >> 5;
    const int sub = wid & 3, half = wid >> 2;
    const int rowl = sub * 32 + lane;

    float* crow = dsm + rowl * 132 + half * 64;
    float sum = 0.f;
    #pragma unroll
    for (int j = 0; j < 64; j += 4) {
        float4 f = *(const float4*)(crow + j);
        f.x = __expf(f.x); f.y = __expf(f.y);
        f.z = __expf(f.z); f.w = __expf(f.w);
        sum += f.x + f.y + f.z + f.w;
        *(float4*)(crow + j) = f;
    }

    float* rsum = dsm + 32768;  // aux region past the 3x stage buffers
    if (half == 0) rsum[rowl] = sum;
    __syncthreads();
    if (half == 1)
        g_spart[((size_t)bh * S_ + blockIdx.y * 128 + rowl) * 16 + blockIdx.x]
            = rsum[rowl] + sum;

    // Coalesced copy Cstage -> g_scores
    float* orow = g_scores + ((size_t)bh * S_ + blockIdx.y * 128) * S_
                + blockIdx.x * 128;
    for (int r = wid; r < 128; r += 8) {
        float4 f = *(const float4*)(dsm + r * 132 + lane * 4);
        *(float4*)(orow + (size_t)r * S_ + lane * 4) = f;
    }
}

// ---------------------------------------------------------------------------
// Kernel 3: PV (1xTF32): (P @ V) / rowsum -> g_ao
// ---------------------------------------------------------------------------
__global__ __launch_bounds__(256) void k_gemm_pv()
{
    extern __shared__ __align__(16) float dsm[];
    const int bh = blockIdx.z;
    const int row0 = blockIdx.y * 128;
    const float* A  = g_scores + ((size_t)bh * S_ + row0) * S_;
    const float* Bm = g_vT + (size_t)bh * DH_ * S_;
    gemm_tile<64, false>(A, S_, Bm, S_, S_, dsm);

    const int tid = threadIdx.x, lane = tid & 31, wid = tid >> 5;
    const int sub = wid & 3, half = wid >> 2;
    const int rowl = sub * 32 + lane;
    const int qrow = row0 + rowl;

    const float* sp = g_spart + ((size_t)bh * S_ + qrow) * 16;
    float tot = 0.f;
    #pragma unroll
    for (int i = 0; i < 16; ++i) tot += __ldg(sp + i);
    const float inv = 1.0f / tot;

    const int b = bh >> 4, h = bh & 15;
    const float* crow = dsm + rowl * 68 + half * 32;
    float* dst = g_ao + (size_t)(b * S_ + qrow) * D_ + h * 64 + half * 32;
    #pragma unroll
    for (int j = 0; j < 32; j += 4) {
        float4 f = *(const float4*)(crow + j);
        float4 o = {f.x * inv, f.y * inv, f.z * inv, f.w * inv};
        *(float4*)(dst + j) = o;
    }
}

// ---------------------------------------------------------------------------
// Kernel 4: output projection (1xTF32)
// ---------------------------------------------------------------------------
__global__ __launch_bounds__(256) void k_gemm_out(
    const float* __restrict__ bias, float* __restrict__ out)
{
    extern __shared__ __align__(16) float dsm[];
    const float* A  = g_ao + (size_t)blockIdx.y * 128 * D_;
    const float* Bm = g_woutT + (size_t)blockIdx.x * 128 * D_;
    gemm_tile<128, false>(A, D_, Bm, D_, D_, dsm);

    const int tid = threadIdx.x, lane = tid & 31, wid = tid >> 5;
    const int sub = wid & 3, half = wid >> 2;
    const int rowl = sub * 32 + lane;

    const float* crow = dsm + rowl * 132 + half * 64;
    const int gm  = blockIdx.y * 128 + rowl;
    const int gn0 = blockIdx.x * 128 + half * 64;
    float* dst = out + (size_t)gm * D_ + gn0;
    #pragma unroll
    for (int j = 0; j < 64; j += 4) {
        float4 f = *(const float4*)(crow + j);
        float4 o = {f.x + __ldg(bias + gn0 + j),
                    f.y + __ldg(bias + gn0 + j + 1),
                    f.z + __ldg(bias + gn0 + j + 2),
                    f.w + __ldg(bias + gn0 + j + 3)};
        *(float4*)(dst + j) = o;
    }
}

// ---------------------------------------------------------------------------
extern "C" void kernel_launch(void* const* d_in, const int* in_sizes, int n_in,
                              void* d_out, int out_size)
{
    (void)in_sizes; (void)n_in; (void)out_size;
    const float* x     = (const float*)d_in[0];
    const float* w_qkv = (const float*)d_in[1];
    const float* b_qkv = (const float*)d_in[2];
    const float* w_out = (const float*)d_in[3];
    const float* b_out = (const float*)d_in[4];
    float* out = (float*)d_out;

    cudaFuncSetAttribute(k_gemm_qkv,    cudaFuncAttributeMaxDynamicSharedMemorySize, DYN_3X);
    cudaFuncSetAttribute(k_gemm_scores, cudaFuncAttributeMaxDynamicSharedMemorySize, DYN_3X);
    cudaFuncSetAttribute(k_gemm_pv,     cudaFuncAttributeMaxDynamicSharedMemorySize, DYN_PV);
    cudaFuncSetAttribute(k_gemm_out,    cudaFuncAttributeMaxDynamicSharedMemorySize, DYN_OUT);

    k_transpose<<<dim3(96, 32), dim3(32, 8)>>>(w_qkv, D_, 3 * D_, 0);
    k_transpose<<<dim3(32, 32), dim3(32, 8)>>>(w_out, D_, D_, 1);

    k_gemm_qkv<<<dim3(24, 64), 256, DYN_3X>>>(x, b_qkv);
    k_gemm_scores<<<dim3(16, 16, 64), 256, DYN_3X>>>();
    k_gemm_pv<<<dim3(1, 16, 64), 256, DYN_PV>>>();
    k_gemm_out<<<dim3(8, 64), 256, DYN_OUT>>>(b_out, out);
}

// round 5
// speedup vs baseline: 4.6309x; 2.1860x over previous
#include <cuda_runtime.h>
#include <cuda_bf16.h>
#include <cuda_fp16.h>
#include <math.h>

typedef unsigned int u32;

#define D_ 1024
#define S_ 2048
#define BH_ 64
#define SCALE_ 0.125f

// ---------------- device-global scratch ------------------------------------
__device__ float  g_q    [(size_t)BH_ * S_ * 64];   // [bh][s][dh] fp32 (scaled)
__device__ float  g_k    [(size_t)BH_ * S_ * 64];
__device__ __half g_vh   [(size_t)BH_ * S_ * 64];   // [bh][s][dh]
__device__ __half g_vTh  [(size_t)BH_ * 64 * S_];   // [bh][dh][s]
__device__ __half g_ph   [(size_t)BH_ * S_ * S_];   // exp(scores) fp16
__device__ float  g_spart[(size_t)BH_ * S_ * 16];
__device__ float  g_rtot [(size_t)BH_ * S_];
__device__ __half g_aoh  [(size_t)8192 * D_];       // [tok][1024]
__device__ float  g_wqkvT[(size_t)3 * D_ * D_];     // [n][k] fp32
__device__ __half g_woutTh[(size_t)D_ * D_];        // [n][k] fp16

// ---------------- helpers ----------------------------------------------------
__device__ __forceinline__ u32 smem_u32(const void* p) {
    u32 a;
    asm("{ .reg .u64 t; cvta.to.shared.u64 t, %1; cvt.u32.u64 %0, t; }" : "=r"(a) : "l"(p));
    return a;
}
#define CP16(s, g) asm volatile("cp.async.cg.shared.global [%0], [%1], 16;" :: "r"(s), "l"(g))
#define CPC        asm volatile("cp.async.commit_group;")
#define CPW(n)     asm volatile("cp.async.wait_group %0;" :: "n"(n))

__device__ __forceinline__ void bfsplit2(float a, float b, u32& hi, u32& lo) {
    __nv_bfloat162 h = __floats2bfloat162_rn(a, b);
    float2 hf = __bfloat1622float2(h);
    __nv_bfloat162 l = __floats2bfloat162_rn(a - hf.x, b - hf.y);
    hi = *(u32*)&h; lo = *(u32*)&l;
}

#define MMA_BF16(c, a0,a1,a2,a3, b0,b1) asm volatile( \
    "mma.sync.aligned.m16n8k16.row.col.f32.bf16.bf16.f32 " \
    "{%0,%1,%2,%3},{%4,%5,%6,%7},{%8,%9},{%0,%1,%2,%3};" \
    : "+f"((c)[0]), "+f"((c)[1]), "+f"((c)[2]), "+f"((c)[3]) \
    : "r"(a0), "r"(a1), "r"(a2), "r"(a3), "r"(b0), "r"(b1))

#define MMA_F16(c, a0,a1,a2,a3, b0,b1) asm volatile( \
    "mma.sync.aligned.m16n8k16.row.col.f32.f16.f16.f32 " \
    "{%0,%1,%2,%3},{%4,%5,%6,%7},{%8,%9},{%0,%1,%2,%3};" \
    : "+f"((c)[0]), "+f"((c)[1]), "+f"((c)[2]), "+f"((c)[3]) \
    : "r"(a0), "r"(a1), "r"(a2), "r"(a3), "r"(b0), "r"(b1))

// ============================================================================
// bf16 3-term GEMM: C[128x128] = A[128xK] @ B[128xK]^T, fp32 inputs.
// 8 warps 2x4. Smem fragment-order, hi/lo interleaved per lane (uint2 loads).
// Register-staged double buffer, one syncthreads per 32-K chunk.
// ============================================================================
template <int NCH>
__device__ __forceinline__ void gemm3_run(
    const float* __restrict__ A, int lda,
    const float* __restrict__ Bm, int ldb,
    char* dsm, float (&c)[4][4][4])
{
    const int tid = threadIdx.x, lane = tid & 31, wid = tid >> 5;
    const int wm = wid >> 2, wn = wid & 3;
    constexpr int STG = 32768, OFFB = 16384;

    float4 ra[4], rb[4];
    auto gload = [&](int k0) {
        #pragma unroll
        for (int p = 0; p < 4; ++p) {
            int idx = tid + (p << 8);
            ra[p] = *(const float4*)(A + (size_t)(idx >> 3) * lda + k0 + ((idx & 7) << 2));
        }
        #pragma unroll
        for (int p = 0; p < 4; ++p) {
            int idx = tid + (p << 8);
            rb[p] = *(const float4*)(Bm + (size_t)(idx >> 3) * ldb + k0 + ((idx & 7) << 2));
        }
    };
    auto stage = [&](int buf) {
        char* st = dsm + buf * STG;
        #pragma unroll
        for (int p = 0; p < 4; ++p) {
            int idx = tid + (p << 8);
            int row = idx >> 3, kk = (idx & 7) << 2;
            int f  = ((row >> 4) * 2 + (kk >> 4)) * 4 + ((row >> 3) & 1) + (((kk >> 3) & 1) << 1);
            int l0 = (row & 7) * 4 + ((kk & 7) >> 1);
            u32 h0, lo0, h1, lo1; float4 v = ra[p];
            bfsplit2(v.x, v.y, h0, lo0); bfsplit2(v.z, v.w, h1, lo1);
            *(uint4*)(st + (f * 64 + l0 * 2) * 4) = make_uint4(h0, lo0, h1, lo1);
        }
        #pragma unroll
        for (int p = 0; p < 4; ++p) {
            int idx = tid + (p << 8);
            int n = idx >> 3, kk = (idx & 7) << 2;
            int f  = ((n >> 3) * 2 + (kk >> 4)) * 2 + ((kk >> 3) & 1);
            int l0 = (n & 7) * 4 + ((kk & 7) >> 1);
            u32 h0, lo0, h1, lo1; float4 v = rb[p];
            bfsplit2(v.x, v.y, h0, lo0); bfsplit2(v.z, v.w, h1, lo1);
            *(uint4*)(st + OFFB + (f * 64 + l0 * 2) * 4) = make_uint4(h0, lo0, h1, lo1);
        }
    };

    gload(0); stage(0); __syncthreads();
    for (int ch = 0; ch < NCH; ++ch) {
        if (ch + 1 < NCH) gload((ch + 1) << 5);
        const char* st = dsm + (ch & 1) * STG;
        #pragma unroll
        for (int kt = 0; kt < 2; ++kt) {
            u32 bhf[4][2], blf[4][2];
            #pragma unroll
            for (int nt = 0; nt < 4; ++nt)
                #pragma unroll
                for (int r = 0; r < 2; ++r) {
                    uint2 v = *(const uint2*)(st + OFFB
                        + ((((wn * 4 + nt) * 2 + kt) * 2 + r) * 64 + lane * 2) * 4);
                    bhf[nt][r] = v.x; blf[nt][r] = v.y;
                }
            #pragma unroll
            for (int mt = 0; mt < 4; ++mt) {
                u32 ah[4], al[4];
                #pragma unroll
                for (int r = 0; r < 4; ++r) {
                    uint2 v = *(const uint2*)(st
                        + ((((wm * 4 + mt) * 2 + kt) * 4 + r) * 64 + lane * 2) * 4);
                    ah[r] = v.x; al[r] = v.y;
                }
                #pragma unroll
                for (int nt = 0; nt < 4; ++nt) {
                    MMA_BF16(c[mt][nt], ah[0],ah[1],ah[2],ah[3], bhf[nt][0],bhf[nt][1]);
                    MMA_BF16(c[mt][nt], ah[0],ah[1],ah[2],ah[3], blf[nt][0],blf[nt][1]);
                    MMA_BF16(c[mt][nt], al[0],al[1],al[2],al[3], bhf[nt][0],bhf[nt][1]);
                }
            }
        }
        if (ch + 1 < NCH) stage((ch + 1) & 1);
        __syncthreads();
    }
}

// ============================================================================
// fp16 1x GEMM: C[128xBN] = A[128xK] @ B[BNxK]^T, half inputs, cp.async.
// ============================================================================
template <int BN, int MT, int WN, int NCH, int STAGES>
__device__ __forceinline__ void gemm16_run(
    const __half* __restrict__ A, int lda,
    const __half* __restrict__ Bm, int ldb,
    char* dsm, u32 sb, float (&c)[MT][4][4])
{
    const int tid = threadIdx.x, lane = tid & 31, wid = tid >> 5;
    const int wm = wid / WN, wn = wid % WN;
    constexpr int ASTG = 8192;
    constexpr int BSTG = BN * 64;
    constexpr int STG  = ASTG + BSTG;
    constexpr int PB   = (BN * 4) / 256;

    u32 sA[2]; const __half* gA[2];
    #pragma unroll
    for (int p = 0; p < 2; ++p) {
        int idx = tid + (p << 8);
        int row = idx >> 2, k8 = (idx & 3) * 8;
        int f = ((row >> 4) * 2 + (k8 >> 4)) * 4 + ((row >> 3) & 1) + (((k8 >> 3) & 1) << 1);
        sA[p] = sb + (u32)((f * 32 + (row & 7) * 4) * 4);
        gA[p] = A + (size_t)row * lda + k8;
    }
    u32 sB[PB]; const __half* gB[PB];
    #pragma unroll
    for (int p = 0; p < PB; ++p) {
        int idx = tid + (p << 8);
        int n = idx >> 2, k8 = (idx & 3) * 8;
        int f = ((n >> 3) * 2 + (k8 >> 4)) * 2 + ((k8 >> 3) & 1);
        sB[p] = sb + ASTG + (u32)((f * 32 + (n & 7) * 4) * 4);
        gB[p] = Bm + (size_t)n * ldb + k8;
    }
    auto load = [&](int s) {
        u32 off = (u32)((s % STAGES) * STG);
        int k0 = s << 5;
        #pragma unroll
        for (int p = 0; p < 2; ++p) CP16(sA[p] + off, gA[p] + k0);
        #pragma unroll
        for (int p = 0; p < PB; ++p) CP16(sB[p] + off, gB[p] + k0);
        CPC;
    };
    #pragma unroll
    for (int s = 0; s < STAGES - 1; ++s) { if (s < NCH) load(s); else CPC; }

    for (int ch = 0; ch < NCH; ++ch) {
        CPW(STAGES - 2);
        __syncthreads();
        if (ch + STAGES - 1 < NCH) load(ch + STAGES - 1); else CPC;
        const char* st = dsm + (ch % STAGES) * STG;
        #pragma unroll
        for (int kt = 0; kt < 2; ++kt) {
            u32 br[4][2];
            #pragma unroll
            for (int nt = 0; nt < 4; ++nt)
                #pragma unroll
                for (int r = 0; r < 2; ++r)
                    br[nt][r] = *(const u32*)(st + ASTG
                        + ((((wn * 4 + nt) * 2 + kt) * 2 + r) * 32 + lane) * 4);
            #pragma unroll
            for (int mt = 0; mt < MT; ++mt) {
                u32 ar[4];
                #pragma unroll
                for (int r = 0; r < 4; ++r)
                    ar[r] = *(const u32*)(st
                        + ((((wm * MT + mt) * 2 + kt) * 4 + r) * 32 + lane) * 4);
                #pragma unroll
                for (int nt = 0; nt < 4; ++nt)
                    MMA_F16(c[mt][nt], ar[0],ar[1],ar[2],ar[3], br[nt][0],br[nt][1]);
            }
        }
    }
    __syncthreads();
}

#define ZERO_C(c, MT) { _Pragma("unroll") for (int m = 0; m < MT; ++m) \
    _Pragma("unroll") for (int n = 0; n < 4; ++n) \
    _Pragma("unroll") for (int r = 0; r < 4; ++r) (c)[m][n][r] = 0.f; }

// ---------------- prep kernels ----------------------------------------------
__global__ __launch_bounds__(256) void k_wqkvT(const float* __restrict__ w)
{
    __shared__ float tile[32][33];
    int bx = blockIdx.x * 32, by = blockIdx.y * 32;   // bx: n(3072), by: k(1024)
    int tx = threadIdx.x, ty = threadIdx.y;
    #pragma unroll
    for (int i = 0; i < 32; i += 8)
        tile[ty + i][tx] = w[(size_t)(by + ty + i) * (3 * D_) + bx + tx];
    __syncthreads();
    #pragma unroll
    for (int i = 0; i < 32; i += 8)
        g_wqkvT[(size_t)(bx + ty + i) * D_ + by + tx] = tile[tx][ty + i];
}

__global__ __launch_bounds__(256) void k_woutT(const float* __restrict__ w)
{
    __shared__ float tile[32][33];
    int bx = blockIdx.x * 32, by = blockIdx.y * 32;
    int tx = threadIdx.x, ty = threadIdx.y;
    #pragma unroll
    for (int i = 0; i < 32; i += 8)
        tile[ty + i][tx] = w[(size_t)(by + ty + i) * D_ + bx + tx];
    __syncthreads();
    #pragma unroll
    for (int i = 0; i < 32; i += 8)
        g_woutTh[(size_t)(bx + ty + i) * D_ + by + tx] = __float2half(tile[tx][ty + i]);
}

__global__ void k_vT()
{
    __shared__ __half tile[32][33];
    int bh = blockIdx.z, s0 = blockIdx.x * 32, d0 = blockIdx.y * 32;
    int tx = threadIdx.x, ty = threadIdx.y;
    const __half* src = g_vh + (size_t)bh * S_ * 64;
    __half* dst = g_vTh + (size_t)bh * 64 * S_;
    #pragma unroll
    for (int i = 0; i < 32; i += 8)
        tile[ty + i][tx] = src[(size_t)(s0 + ty + i) * 64 + d0 + tx];
    __syncthreads();
    #pragma unroll
    for (int i = 0; i < 32; i += 8)
        dst[(size_t)(d0 + ty + i) * S_ + s0 + tx] = tile[tx][ty + i];
}

__global__ void k_rowsum()
{
    int i = blockIdx.x * 256 + threadIdx.x;
    const float* sp = g_spart + (size_t)i * 16;
    float t = 0.f;
    #pragma unroll
    for (int j = 0; j < 16; ++j) t += sp[j];
    g_rtot[i] = t;
}

// ---------------- kernel 1: QKV projection (bf16-3x) ------------------------
__global__ __launch_bounds__(256, 2) void k_qkv(
    const float* __restrict__ x, const float* __restrict__ bias)
{
    extern __shared__ __align__(16) char dsm[];
    const int row0 = blockIdx.y * 128, col0 = blockIdx.x * 128;
    float c[4][4][4]; ZERO_C(c, 4);
    gemm3_run<32>(x + (size_t)row0 * D_, D_, g_wqkvT + (size_t)col0 * D_, D_, dsm, c);

    const int lane = threadIdx.x & 31, wid = threadIdx.x >> 5;
    const int wm = wid >> 2, wn = wid & 3, g = lane >> 2, t = lane & 3;
    const int three = col0 >> 10;
    #pragma unroll
    for (int nt = 0; nt < 4; ++nt) {
        int gcol = col0 + wn * 32 + nt * 8 + t * 2;
        float b0 = __ldg(bias + gcol), b1 = __ldg(bias + gcol + 1);
        int h = (gcol >> 6) & 15, dh = gcol & 63;
        #pragma unroll
        for (int mt = 0; mt < 4; ++mt)
            #pragma unroll
            for (int hh = 0; hh < 2; ++hh) {
                int gm = row0 + wm * 64 + mt * 16 + hh * 8 + g;
                int b = gm >> 11, s = gm & 2047;
                size_t base = ((size_t)(b * 16 + h) * S_ + s) * 64 + dh;
                float v0 = c[mt][nt][hh * 2] + b0, v1 = c[mt][nt][hh * 2 + 1] + b1;
                if (three == 0) {
                    *(float2*)(g_q + base) = make_float2(v0 * SCALE_, v1 * SCALE_);
                } else if (three == 1) {
                    *(float2*)(g_k + base) = make_float2(v0, v1);
                } else {
                    __half2 hv = __floats2half2_rn(v0, v1);
                    *(u32*)(g_vh + base) = *(u32*)&hv;
                }
            }
    }
}

// ---------------- kernel 2: scores = exp(QK^T) (bf16-3x) --------------------
__global__ __launch_bounds__(256, 2) void k_scores()
{
    extern __shared__ __align__(16) char dsm[];
    const int bh = blockIdx.z, row0 = blockIdx.y * 128, col0 = blockIdx.x * 128;
    float c[4][4][4]; ZERO_C(c, 4);
    gemm3_run<2>(g_q + ((size_t)bh * S_ + row0) * 64, 64,
                 g_k + ((size_t)bh * S_ + col0) * 64, 64, dsm, c);

    const int tid = threadIdx.x, lane = tid & 31, wid = tid >> 5;
    const int wm = wid >> 2, wn = wid & 3, g = lane >> 2, t = lane & 3;
    float* rs = (float*)(dsm + 65536);
    #pragma unroll
    for (int mt = 0; mt < 4; ++mt)
        #pragma unroll
        for (int hh = 0; hh < 2; ++hh) {
            int row = wm * 64 + mt * 16 + hh * 8 + g;
            float ps = 0.f;
            #pragma unroll
            for (int nt = 0; nt < 4; ++nt) {
                float e0 = __expf(c[mt][nt][hh * 2]);
                float e1 = __expf(c[mt][nt][hh * 2 + 1]);
                ps += e0 + e1;
                __half2 p2 = __floats2half2_rn(e0, e1);
                *(u32*)(dsm + row * 272 + (wn * 32 + nt * 8 + t * 2) * 2) = *(u32*)&p2;
            }
            ps += __shfl_xor_sync(0xffffffffu, ps, 1);
            ps += __shfl_xor_sync(0xffffffffu, ps, 2);
            if (t == 0) rs[row * 4 + wn] = ps;
        }
    __syncthreads();
    if (tid < 128) {
        float s4 = rs[tid * 4] + rs[tid * 4 + 1] + rs[tid * 4 + 2] + rs[tid * 4 + 3];
        g_spart[((size_t)bh * S_ + row0 + tid) * 16 + blockIdx.x] = s4;
    }
    __half* pb = g_ph + ((size_t)bh * S_ + row0) * S_ + col0;
    for (int i = tid; i < 2048; i += 256) {
        int r = i >> 4, c16 = i & 15;
        *(uint4*)(pb + (size_t)r * S_ + c16 * 8) = *(const uint4*)(dsm + r * 272 + c16 * 16);
    }
}

// ---------------- kernel 3: PV (fp16 1x) -------------------------------------
__global__ __launch_bounds__(256, 2) void k_pv()
{
    extern __shared__ __align__(16) char dsm[];
    u32 sb = smem_u32(dsm);
    const int bh = blockIdx.y, row0 = blockIdx.x * 128;
    float c[2][4][4]; ZERO_C(c, 2);
    gemm16_run<64, 2, 2, 64, 4>(g_ph + ((size_t)bh * S_ + row0) * S_, S_,
                                g_vTh + (size_t)bh * 64 * S_, S_, dsm, sb, c);

    const int lane = threadIdx.x & 31, wid = threadIdx.x >> 5;
    const int wm = wid >> 1, wn = wid & 1, g = lane >> 2, t = lane & 3;
    const int b = bh >> 4, h = bh & 15;
    #pragma unroll
    for (int mt = 0; mt < 2; ++mt)
        #pragma unroll
        for (int hh = 0; hh < 2; ++hh) {
            int row = wm * 32 + mt * 16 + hh * 8 + g;
            float inv = 1.0f / __ldg(g_rtot + (size_t)bh * S_ + row0 + row);
            size_t tok = (size_t)b * S_ + row0 + row;
            #pragma unroll
            for (int nt = 0; nt < 4; ++nt) {
                int dh = wn * 32 + nt * 8 + t * 2;
                __half2 o = __floats2half2_rn(c[mt][nt][hh * 2] * inv,
                                              c[mt][nt][hh * 2 + 1] * inv);
                *(u32*)(g_aoh + tok * D_ + h * 64 + dh) = *(u32*)&o;
            }
        }
}

// ---------------- kernel 4: output projection (fp16 1x) ----------------------
__global__ __launch_bounds__(256, 2) void k_out(
    const float* __restrict__ bias, float* __restrict__ out)
{
    extern __shared__ __align__(16) char dsm[];
    u32 sb = smem_u32(dsm);
    const int row0 = blockIdx.y * 128, col0 = blockIdx.x * 128;
    float c[4][4][4]; ZERO_C(c, 4);
    gemm16_run<128, 4, 4, 32, 3>(g_aoh + (size_t)row0 * D_, D_,
                                 g_woutTh + (size_t)col0 * D_, D_, dsm, sb, c);

    const int lane = threadIdx.x & 31, wid = threadIdx.x >> 5;
    const int wm = wid >> 2, wn = wid & 3, g = lane >> 2, t = lane & 3;
    #pragma unroll
    for (int nt = 0; nt < 4; ++nt) {
        int gcol = col0 + wn * 32 + nt * 8 + t * 2;
        float b0 = __ldg(bias + gcol), b1 = __ldg(bias + gcol + 1);
        #pragma unroll
        for (int mt = 0; mt < 4; ++mt)
            #pragma unroll
            for (int hh = 0; hh < 2; ++hh) {
                int gm = row0 + wm * 64 + mt * 16 + hh * 8 + g;
                *(float2*)(out + (size_t)gm * D_ + gcol) =
                    make_float2(c[mt][nt][hh * 2] + b0, c[mt][nt][hh * 2 + 1] + b1);
            }
    }
}

// ---------------------------------------------------------------------------
#define DYN_3X 67584
#define DYN_16 49152

extern "C" void kernel_launch(void* const* d_in, const int* in_sizes, int n_in,
                              void* d_out, int out_size)
{
    (void)in_sizes; (void)n_in; (void)out_size;
    const float* x     = (const float*)d_in[0];
    const float* w_qkv = (const float*)d_in[1];
    const float* b_qkv = (const float*)d_in[2];
    const float* w_out = (const float*)d_in[3];
    const float* b_out = (const float*)d_in[4];
    float* out = (float*)d_out;

    cudaFuncSetAttribute(k_qkv,    cudaFuncAttributeMaxDynamicSharedMemorySize, DYN_3X);
    cudaFuncSetAttribute(k_scores, cudaFuncAttributeMaxDynamicSharedMemorySize, DYN_3X);
    cudaFuncSetAttribute(k_pv,     cudaFuncAttributeMaxDynamicSharedMemorySize, DYN_16);
    cudaFuncSetAttribute(k_out,    cudaFuncAttributeMaxDynamicSharedMemorySize, DYN_16);

    k_wqkvT<<<dim3(96, 32), dim3(32, 8)>>>(w_qkv);
    k_woutT<<<dim3(32, 32), dim3(32, 8)>>>(w_out);

    k_qkv<<<dim3(24, 64), 256, DYN_3X>>>(x, b_qkv);
    k_vT<<<dim3(64, 2, 64), dim3(32, 8)>>>();
    k_scores<<<dim3(16, 16, 64), 256, DYN_3X>>>();
    k_rowsum<<<512, 256>>>();
    k_pv<<<dim3(16, 64), 256, DYN_16>>>();
    k_out<<<dim3(8, 64), 256, DYN_16>>>(b_out, out);
}

// round 7
// speedup vs baseline: 6.4227x; 1.3869x over previous
#include <cuda_runtime.h>
#include <cuda_bf16.h>
#include <cuda_fp16.h>
#include <math.h>

typedef unsigned int u32;

#define D_ 1024
#define S_ 2048
#define BH_ 64
#define SCALE_ 0.125f

// ---------------- device-global scratch ------------------------------------
__device__ u32    g_xp  [(size_t)8192 * 1024];      // x pairs [tok][1024]
__device__ u32    g_wqp [(size_t)3072 * 1024];      // w_qkv^T pairs [n][1024]
__device__ u32    g_qp  [(size_t)BH_ * S_ * 64];    // q pairs [bh][s][64] (scaled)
__device__ u32    g_kp  [(size_t)BH_ * S_ * 64];    // k pairs
__device__ __half g_vh  [(size_t)BH_ * S_ * 64];    // [bh][s][dh]
__device__ __half g_vTh [(size_t)BH_ * 64 * S_];    // [bh][dh][s]
__device__ __half g_aoh [(size_t)8192 * D_];        // attention out fp16
__device__ __half g_woutTh[(size_t)D_ * D_];        // w_out^T fp16 [n][k]

// ---------------- helpers ----------------------------------------------------
__device__ __forceinline__ u32 smem_u32(const void* p) {
    u32 a;
    asm("{ .reg .u64 t; cvta.to.shared.u64 t, %1; cvt.u32.u64 %0, t; }" : "=r"(a) : "l"(p));
    return a;
}
#define CP16(s, g) asm volatile("cp.async.cg.shared.global [%0], [%1], 16;" :: "r"(s), "l"(g))
#define CPC        asm volatile("cp.async.commit_group;")
#define CPW(n)     asm volatile("cp.async.wait_group %0;" :: "n"(n))

__device__ __forceinline__ void bfsplit2(float a, float b, u32& hi, u32& lo) {
    __nv_bfloat162 h = __floats2bfloat162_rn(a, b);
    float2 hf = __bfloat1622float2(h);
    __nv_bfloat162 l = __floats2bfloat162_rn(a - hf.x, b - hf.y);
    hi = *(u32*)&h; lo = *(u32*)&l;
}

#define MMA_BF16(c, a0,a1,a2,a3, b0,b1) asm volatile( \
    "mma.sync.aligned.m16n8k16.row.col.f32.bf16.bf16.f32 " \
    "{%0,%1,%2,%3},{%4,%5,%6,%7},{%8,%9},{%0,%1,%2,%3};" \
    : "+f"((c)[0]), "+f"((c)[1]), "+f"((c)[2]), "+f"((c)[3]) \
    : "r"(a0), "r"(a1), "r"(a2), "r"(a3), "r"(b0), "r"(b1))

#define MMA_F16(c, a0,a1,a2,a3, b0,b1) asm volatile( \
    "mma.sync.aligned.m16n8k16.row.col.f32.f16.f16.f32 " \
    "{%0,%1,%2,%3},{%4,%5,%6,%7},{%8,%9},{%0,%1,%2,%3};" \
    : "+f"((c)[0]), "+f"((c)[1]), "+f"((c)[2]), "+f"((c)[3]) \
    : "r"(a0), "r"(a1), "r"(a2), "r"(a3), "r"(b0), "r"(b1))

#define ZERO_C3(c, MT) { _Pragma("unroll") for (int m = 0; m < MT; ++m) \
    _Pragma("unroll") for (int n = 0; n < 4; ++n) \
    _Pragma("unroll") for (int r = 0; r < 4; ++r) (c)[m][n][r] = 0.f; }

#define ZERO_C2(c, NT) { _Pragma("unroll") for (int n = 0; n < NT; ++n) \
    _Pragma("unroll") for (int r = 0; r < 4; ++r) (c)[n][r] = 0.f; }

// ============================================================================
// Prep kernels
// ============================================================================
__global__ __launch_bounds__(256) void k_splitx(const float* __restrict__ x)
{
    size_t row = blockIdx.x;
    int j = threadIdx.x;
    float4 v = *(const float4*)(x + row * D_ + j * 4);
    u32 h0, l0, h1, l1;
    bfsplit2(v.x, v.y, h0, l0);
    bfsplit2(v.z, v.w, h1, l1);
    *(uint4*)(g_xp + row * 1024 + j * 4) = make_uint4(h0, l0, h1, l1);
}

__global__ __launch_bounds__(256) void k_wsplit(const float* __restrict__ w)
{
    __shared__ float tile[32][33];
    int bx = blockIdx.x * 32, by = blockIdx.y * 32;   // bx: n(3072), by: k(1024)
    int tx = threadIdx.x, ty = threadIdx.y;
    #pragma unroll
    for (int i = 0; i < 32; i += 8)
        tile[ty + i][tx] = w[(size_t)(by + ty + i) * 3072 + bx + tx];
    __syncthreads();
    if (tx < 16) {
        #pragma unroll
        for (int i = 0; i < 4; ++i) {
            int r = ty + i * 8;
            u32 hi, lo;
            bfsplit2(tile[2 * tx][r], tile[2 * tx + 1][r], hi, lo);
            *(uint2*)(g_wqp + (size_t)(bx + r) * 1024 + by + 2 * tx) = make_uint2(hi, lo);
        }
    }
}

__global__ __launch_bounds__(256) void k_woutT(const float* __restrict__ w)
{
    __shared__ float tile[32][33];
    int bx = blockIdx.x * 32, by = blockIdx.y * 32;
    int tx = threadIdx.x, ty = threadIdx.y;
    #pragma unroll
    for (int i = 0; i < 32; i += 8)
        tile[ty + i][tx] = w[(size_t)(by + ty + i) * D_ + bx + tx];
    __syncthreads();
    #pragma unroll
    for (int i = 0; i < 32; i += 8)
        g_woutTh[(size_t)(bx + ty + i) * D_ + by + tx] = __float2half(tile[tx][ty + i]);
}

__global__ void k_vT()
{
    __shared__ __half tile[32][33];
    int bh = blockIdx.z, s0 = blockIdx.x * 32, d0 = blockIdx.y * 32;
    int tx = threadIdx.x, ty = threadIdx.y;
    const __half* src = g_vh + (size_t)bh * S_ * 64;
    __half* dst = g_vTh + (size_t)bh * 64 * S_;
    #pragma unroll
    for (int i = 0; i < 32; i += 8)
        tile[ty + i][tx] = src[(size_t)(s0 + ty + i) * 64 + d0 + tx];
    __syncthreads();
    #pragma unroll
    for (int i = 0; i < 32; i += 8)
        dst[(size_t)(d0 + ty + i) * S_ + s0 + tx] = tile[tx][ty + i];
}

// ============================================================================
// Kernel 1: QKV projection. bf16-3x pair-format gemm, 128x128 tile, cp.async.
// ============================================================================
#define QKV_STG 32768
__global__ __launch_bounds__(256, 2) void k_qkv(const float* __restrict__ bias)
{
    extern __shared__ __align__(16) char dsm[];
    u32 sb = smem_u32(dsm);
    const int tid = threadIdx.x, lane = tid & 31, wid = tid >> 5;
    const int wm = wid >> 2, wn = wid & 3;
    const int row0 = blockIdx.y * 128, col0 = blockIdx.x * 128;

    const u32* A = g_xp + (size_t)row0 * 1024;
    const u32* B = g_wqp + (size_t)col0 * 1024;

    u32 aOff[4]; const u32* aG[4];
    u32 bOff[4]; const u32* bG[4];
    #pragma unroll
    for (int p = 0; p < 4; ++p) {
        int id = tid + p * 256;
        int row = id >> 3, cc = id & 7;
        aOff[p] = sb + (u32)(((((row >> 4) * 2 + (cc >> 2)) * 4
                   + ((row >> 3) & 1) + 2 * ((cc >> 1) & 1)) * 32
                   + (row & 7) * 4 + 2 * (cc & 1)) * 8);
        aG[p] = A + (size_t)row * 1024 + cc * 4;
        bOff[p] = sb + 16384 + (u32)(((((row >> 3) * 2 + (cc >> 2)) * 2
                   + ((cc >> 1) & 1)) * 32 + (row & 7) * 4 + 2 * (cc & 1)) * 8);
        bG[p] = B + (size_t)row * 1024 + cc * 4;
    }
    auto load = [&](int ch) {
        u32 so = (u32)((ch % 3) * QKV_STG);
        int k0 = ch * 32;
        #pragma unroll
        for (int p = 0; p < 4; ++p) CP16(aOff[p] + so, aG[p] + k0);
        #pragma unroll
        for (int p = 0; p < 4; ++p) CP16(bOff[p] + so, bG[p] + k0);
        CPC;
    };
    load(0); load(1);

    float c[4][4][4]; ZERO_C3(c, 4);
    for (int ch = 0; ch < 32; ++ch) {
        CPW(1);
        __syncthreads();
        if (ch + 2 < 32) load(ch + 2); else CPC;
        const char* st = dsm + (ch % 3) * QKV_STG;
        #pragma unroll
        for (int kt = 0; kt < 2; ++kt) {
            u32 bhf[4][2], blf[4][2];
            #pragma unroll
            for (int nt = 0; nt < 4; ++nt)
                #pragma unroll
                for (int r = 0; r < 2; ++r) {
                    uint2 v = *(const uint2*)(st + 16384
                        + ((((wn * 4 + nt) * 2 + kt) * 2 + r) * 32 + lane) * 8);
                    bhf[nt][r] = v.x; blf[nt][r] = v.y;
                }
            #pragma unroll
            for (int mt = 0; mt < 4; ++mt) {
                u32 ah[4], al[4];
                #pragma unroll
                for (int r = 0; r < 4; ++r) {
                    uint2 v = *(const uint2*)(st
                        + ((((wm * 4 + mt) * 2 + kt) * 4 + r) * 32 + lane) * 8);
                    ah[r] = v.x; al[r] = v.y;
                }
                #pragma unroll
                for (int nt = 0; nt < 4; ++nt) {
                    MMA_BF16(c[mt][nt], ah[0],ah[1],ah[2],ah[3], bhf[nt][0],bhf[nt][1]);
                    MMA_BF16(c[mt][nt], ah[0],ah[1],ah[2],ah[3], blf[nt][0],blf[nt][1]);
                    MMA_BF16(c[mt][nt], al[0],al[1],al[2],al[3], bhf[nt][0],bhf[nt][1]);
                }
            }
        }
    }

    const int g = lane >> 2, t = lane & 3;
    const int three = col0 >> 10;
    #pragma unroll
    for (int nt = 0; nt < 4; ++nt) {
        int gcol = col0 + wn * 32 + nt * 8 + t * 2;
        float b0 = __ldg(bias + gcol), b1 = __ldg(bias + gcol + 1);
        int h = (gcol >> 6) & 15, dh = gcol & 63;
        #pragma unroll
        for (int mt = 0; mt < 4; ++mt)
            #pragma unroll
            for (int hh = 0; hh < 2; ++hh) {
                int gm = row0 + wm * 64 + mt * 16 + hh * 8 + g;
                int b = gm >> 11, s = gm & 2047;
                size_t base = ((size_t)(b * 16 + h) * S_ + s) * 64 + dh;
                float v0 = c[mt][nt][hh * 2] + b0, v1 = c[mt][nt][hh * 2 + 1] + b1;
                if (three == 0) {
                    u32 hi, lo; bfsplit2(v0 * SCALE_, v1 * SCALE_, hi, lo);
                    *(uint2*)(g_qp + base) = make_uint2(hi, lo);
                } else if (three == 1) {
                    u32 hi, lo; bfsplit2(v0, v1, hi, lo);
                    *(uint2*)(g_kp + base) = make_uint2(hi, lo);
                } else {
                    __half2 hv = __floats2half2_rn(v0, v1);
                    *(u32*)(g_vh + base) = *(u32*)&hv;
                }
            }
    }
}

// ============================================================================
// Kernel 2: fused flash attention. CTA = 128 q-rows x 1 head. 8 warps m16 each.
// ============================================================================
#define AT_QSZ 32768
#define AT_STG 24576
__global__ __launch_bounds__(256, 2) void k_attn()
{
    extern __shared__ __align__(16) char dsm[];
    u32 sb = smem_u32(dsm);
    const int tid = threadIdx.x, lane = tid & 31, wid = tid >> 5;
    const int g = lane >> 2, t = lane & 3;
    const int bh = blockIdx.y, row0 = blockIdx.x * 128;

    // Q -> smem (fragment order), once
    const u32* qbase = g_qp + ((size_t)bh * S_ + row0) * 64;
    #pragma unroll
    for (int p = 0; p < 8; ++p) {
        int id = tid + p * 256;
        int row = id >> 4, cc = id & 15;
        u32 off = (u32)(((((row >> 4) * 4 + (cc >> 2)) * 4
                 + ((row >> 3) & 1) + 2 * ((cc >> 1) & 1)) * 32
                 + (row & 7) * 4 + 2 * (cc & 1)) * 8);
        CP16(sb + off, qbase + (size_t)row * 64 + cc * 4);
    }
    CPC;

    // KV producer maps
    u32 kOff[4]; const u32* kG[4];
    #pragma unroll
    for (int p = 0; p < 4; ++p) {
        int id = tid + p * 256;
        int n = id >> 4, cc = id & 15;
        kOff[p] = (u32)(((((n >> 3) * 4 + (cc >> 2)) * 2 + ((cc >> 1) & 1)) * 32
                 + (n & 7) * 4 + 2 * (cc & 1)) * 8);
        kG[p] = g_kp + ((size_t)bh * S_ + n) * 64 + cc * 4;
    }
    u32 vOff[2]; const __half* vG[2];
    #pragma unroll
    for (int p = 0; p < 2; ++p) {
        int id = tid + p * 256;
        int n = id >> 3, cc = id & 7;
        vOff[p] = (u32)(16384 + (((n >> 3) * 4 + (cc >> 1)) * 2 + (cc & 1)) * 128
                 + (n & 7) * 16);
        vG[p] = g_vTh + ((size_t)bh * 64 + n) * S_ + cc * 8;
    }
    auto loadKV = [&](int it) {
        u32 so = sb + AT_QSZ + (u32)((it % 3) * AT_STG);
        int kv0 = it * 64;
        #pragma unroll
        for (int p = 0; p < 4; ++p) CP16(so + kOff[p], kG[p] + (size_t)kv0 * 64);
        #pragma unroll
        for (int p = 0; p < 2; ++p) CP16(so + vOff[p], vG[p] + kv0);
        CPC;
    };
    loadKV(0); loadKV(1);

    float c_o[8][4]; ZERO_C2(c_o, 8);
    float ls0 = 0.f, ls1 = 0.f;

    for (int it = 0; it < 32; ++it) {
        CPW(1);
        __syncthreads();
        if (it + 2 < 32) loadKV(it + 2); else CPC;
        const char* stK = dsm + AT_QSZ + (it % 3) * AT_STG;
        const char* stV = stK + 16384;

        float c_s[8][4]; ZERO_C2(c_s, 8);
        #pragma unroll
        for (int f = 0; f < 4; ++f) {
            u32 qh[4], ql[4];
            #pragma unroll
            for (int r = 0; r < 4; ++r) {
                uint2 v = *(const uint2*)(dsm + (((wid * 4 + f) * 4 + r) * 32 + lane) * 8);
                qh[r] = v.x; ql[r] = v.y;
            }
            #pragma unroll
            for (int nt = 0; nt < 8; ++nt) {
                uint2 b0 = *(const uint2*)(stK + (((nt * 4 + f) * 2 + 0) * 32 + lane) * 8);
                uint2 b1 = *(const uint2*)(stK + (((nt * 4 + f) * 2 + 1) * 32 + lane) * 8);
                MMA_BF16(c_s[nt], qh[0],qh[1],qh[2],qh[3], b0.x, b1.x);
                MMA_BF16(c_s[nt], qh[0],qh[1],qh[2],qh[3], b0.y, b1.y);
                MMA_BF16(c_s[nt], ql[0],ql[1],ql[2],ql[3], b0.x, b1.x);
            }
        }

        // exp + pack into PV A-fragments
        u32 ap[4][4];
        #pragma unroll
        for (int nt = 0; nt < 8; ++nt) {
            float e0 = __expf(c_s[nt][0]);
            float e1 = __expf(c_s[nt][1]);
            float e2 = __expf(c_s[nt][2]);
            float e3 = __expf(c_s[nt][3]);
            ls0 += e0 + e1; ls1 += e2 + e3;
            __half2 p01 = __floats2half2_rn(e0, e1);
            __half2 p23 = __floats2half2_rn(e2, e3);
            ap[nt >> 1][(nt & 1) * 2 + 0] = *(u32*)&p01;
            ap[nt >> 1][(nt & 1) * 2 + 1] = *(u32*)&p23;
        }

        // PV
        #pragma unroll
        for (int f2 = 0; f2 < 4; ++f2)
            #pragma unroll
            for (int nt = 0; nt < 8; ++nt) {
                u32 v0 = *(const u32*)(stV + (((nt * 4 + f2) * 2 + 0) * 32 + lane) * 4);
                u32 v1 = *(const u32*)(stV + (((nt * 4 + f2) * 2 + 1) * 32 + lane) * 4);
                MMA_F16(c_o[nt], ap[f2][0],ap[f2][1],ap[f2][2],ap[f2][3], v0, v1);
            }
    }

    // normalize and write
    ls0 += __shfl_xor_sync(0xffffffffu, ls0, 1);
    ls0 += __shfl_xor_sync(0xffffffffu, ls0, 2);
    ls1 += __shfl_xor_sync(0xffffffffu, ls1, 1);
    ls1 += __shfl_xor_sync(0xffffffffu, ls1, 2);
    float inv0 = 1.0f / ls0, inv1 = 1.0f / ls1;

    const int b = bh >> 4, h = bh & 15;
    int r0 = row0 + wid * 16 + g;
    __half* o0 = g_aoh + ((size_t)b * S_ + r0) * D_ + h * 64;
    __half* o1 = o0 + (size_t)8 * D_;
    #pragma unroll
    for (int nt = 0; nt < 8; ++nt) {
        int dh = nt * 8 + t * 2;
        __half2 w0 = __floats2half2_rn(c_o[nt][0] * inv0, c_o[nt][1] * inv0);
        __half2 w1 = __floats2half2_rn(c_o[nt][2] * inv1, c_o[nt][3] * inv1);
        *(u32*)(o0 + dh) = *(u32*)&w0;
        *(u32*)(o1 + dh) = *(u32*)&w1;
    }
}

// ============================================================================
// Kernel 3: output projection (fp16 1x), cp.async 3-stage.
// ============================================================================
__global__ __launch_bounds__(256, 2) void k_out(
    const float* __restrict__ bias, float* __restrict__ out)
{
    extern __shared__ __align__(16) char dsm[];
    u32 sb = smem_u32(dsm);
    const int tid = threadIdx.x, lane = tid & 31, wid = tid >> 5;
    const int wm = wid >> 2, wn = wid & 3;
    const int row0 = blockIdx.y * 128, col0 = blockIdx.x * 128;
    const __half* A = g_aoh + (size_t)row0 * D_;
    const __half* B = g_woutTh + (size_t)col0 * D_;
    constexpr int STG = 16384;

    u32 sA[2]; const __half* gA[2];
    #pragma unroll
    for (int p = 0; p < 2; ++p) {
        int id = tid + p * 256;
        int row = id >> 2, k8 = (id & 3) * 8;
        int f = ((row >> 4) * 2 + (k8 >> 4)) * 4 + ((row >> 3) & 1) + (((k8 >> 3) & 1) << 1);
        sA[p] = sb + (u32)((f * 32 + (row & 7) * 4) * 4);
        gA[p] = A + (size_t)row * D_ + k8;
    }
    u32 sB[2]; const __half* gB[2];
    #pragma unroll
    for (int p = 0; p < 2; ++p) {
        int id = tid + p * 256;
        int n = id >> 2, k8 = (id & 3) * 8;
        int f = ((n >> 3) * 2 + (k8 >> 4)) * 2 + ((k8 >> 3) & 1);
        sB[p] = sb + 8192 + (u32)((f * 32 + (n & 7) * 4) * 4);
        gB[p] = B + (size_t)n * D_ + k8;
    }
    auto load = [&](int s) {
        u32 off = (u32)((s % 3) * STG);
        int k0 = s << 5;
        #pragma unroll
        for (int p = 0; p < 2; ++p) CP16(sA[p] + off, gA[p] + k0);
        #pragma unroll
        for (int p = 0; p < 2; ++p) CP16(sB[p] + off, gB[p] + k0);
        CPC;
    };
    load(0); load(1);

    float c[4][4][4]; ZERO_C3(c, 4);
    for (int ch = 0; ch < 32; ++ch) {
        CPW(1);
        __syncthreads();
        if (ch + 2 < 32) load(ch + 2); else CPC;
        const char* st = dsm + (ch % 3) * STG;
        #pragma unroll
        for (int kt = 0; kt < 2; ++kt) {
            u32 br[4][2];
            #pragma unroll
            for (int nt = 0; nt < 4; ++nt)
                #pragma unroll
                for (int r = 0; r < 2; ++r)
                    br[nt][r] = *(const u32*)(st + 8192
                        + ((((wn * 4 + nt) * 2 + kt) * 2 + r) * 32 + lane) * 4);
            #pragma unroll
            for (int mt = 0; mt < 4; ++mt) {
                u32 ar[4];
                #pragma unroll
                for (int r = 0; r < 4; ++r)
                    ar[r] = *(const u32*)(st
                        + ((((wm * 4 + mt) * 2 + kt) * 4 + r) * 32 + lane) * 4);
                #pragma unroll
                for (int nt = 0; nt < 4; ++nt)
                    MMA_F16(c[mt][nt], ar[0],ar[1],ar[2],ar[3], br[nt][0],br[nt][1]);
            }
        }
    }

    const int g = lane >> 2, t = lane & 3;
    #pragma unroll
    for (int nt = 0; nt < 4; ++nt) {
        int gcol = col0 + wn * 32 + nt * 8 + t * 2;
        float b0 = __ldg(bias + gcol), b1 = __ldg(bias + gcol + 1);
        #pragma unroll
        for (int mt = 0; mt < 4; ++mt)
            #pragma unroll
            for (int hh = 0; hh < 2; ++hh) {
                int gm = row0 + wm * 64 + mt * 16 + hh * 8 + g;
                *(float2*)(out + (size_t)gm * D_ + gcol) =
                    make_float2(c[mt][nt][hh * 2] + b0, c[mt][nt][hh * 2 + 1] + b1);
            }
    }
}

// ---------------------------------------------------------------------------
#define DYN_QKV  (3 * QKV_STG)           // 98304
#define DYN_ATT  (AT_QSZ + 3 * AT_STG)   // 106496
#define DYN_OUT  49152

extern "C" void kernel_launch(void* const* d_in, const int* in_sizes, int n_in,
                              void* d_out, int out_size)
{
    (void)in_sizes; (void)n_in; (void)out_size;
    const float* x     = (const float*)d_in[0];
    const float* w_qkv = (const float*)d_in[1];
    const float* b_qkv = (const float*)d_in[2];
    const float* w_out = (const float*)d_in[3];
    const float* b_out = (const float*)d_in[4];
    float* out = (float*)d_out;

    cudaFuncSetAttribute(k_qkv,  cudaFuncAttributeMaxDynamicSharedMemorySize, DYN_QKV);
    cudaFuncSetAttribute(k_attn, cudaFuncAttributeMaxDynamicSharedMemorySize, DYN_ATT);
    cudaFuncSetAttribute(k_out,  cudaFuncAttributeMaxDynamicSharedMemorySize, DYN_OUT);

    k_splitx<<<8192, 256>>>(x);
    k_wsplit<<<dim3(96, 32), dim3(32, 8)>>>(w_qkv);
    k_woutT<<<dim3(32, 32), dim3(32, 8)>>>(w_out);

    k_qkv<<<dim3(24, 64), 256, DYN_QKV>>>(b_qkv);
    k_vT<<<dim3(64, 2, 64), dim3(32, 8)>>>();
    k_attn<<<dim3(16, 64), 256, DYN_ATT>>>();
    k_out<<<dim3(8, 64), 256, DYN_OUT>>>(b_out, out);
}

// round 8
// speedup vs baseline: 10.9564x; 1.7059x over previous
#include <cuda_runtime.h>
#include <cuda_fp16.h>
#include <math.h>

typedef unsigned int u32;

#define D_ 1024
#define S_ 2048
#define SCALE_ 0.125f

// ---------------- device-global scratch ------------------------------------
__device__ __half g_xh   [(size_t)8192 * 1024];   // x fp16 [tok][1024]
__device__ __half g_wqh  [(size_t)3072 * 1024];   // w_qkv^T fp16 (q rows pre-scaled)
__device__ __half g_qh   [(size_t)64 * S_ * 64];  // [bh][s][dh] (scaled)
__device__ __half g_kh   [(size_t)64 * S_ * 64];
__device__ __half g_vh   [(size_t)64 * S_ * 64];
__device__ __half g_vTh  [(size_t)64 * 64 * S_];  // [bh][dh][s]
__device__ __half g_aoh  [(size_t)8192 * D_];
__device__ __half g_woutTh[(size_t)D_ * D_];

// ---------------- helpers ---------------------------------------------------
__device__ __forceinline__ u32 smem_u32(const void* p) {
    u32 a;
    asm("{ .reg .u64 t; cvta.to.shared.u64 t, %1; cvt.u32.u64 %0, t; }" : "=r"(a) : "l"(p));
    return a;
}
#define CP16(s, g) asm volatile("cp.async.cg.shared.global [%0], [%1], 16;" :: "r"(s), "l"(g))
#define CPC        asm volatile("cp.async.commit_group;")
#define CPW(n)     asm volatile("cp.async.wait_group %0;" :: "n"(n))

#define MMA_F16(c, a0,a1,a2,a3, b0,b1) asm volatile( \
    "mma.sync.aligned.m16n8k16.row.col.f32.f16.f16.f32 " \
    "{%0,%1,%2,%3},{%4,%5,%6,%7},{%8,%9},{%0,%1,%2,%3};" \
    : "+f"((c)[0]), "+f"((c)[1]), "+f"((c)[2]), "+f"((c)[3]) \
    : "r"(a0), "r"(a1), "r"(a2), "r"(a3), "r"(b0), "r"(b1))

#define ZERO_C3(c, MT) { _Pragma("unroll") for (int m = 0; m < MT; ++m) \
    _Pragma("unroll") for (int n = 0; n < 4; ++n) \
    _Pragma("unroll") for (int r = 0; r < 4; ++r) (c)[m][n][r] = 0.f; }

#define ZERO_C2(c, NT) { _Pragma("unroll") for (int n = 0; n < NT; ++n) \
    _Pragma("unroll") for (int r = 0; r < 4; ++r) (c)[n][r] = 0.f; }

// ============================================================================
// Shared fp16 1x GEMM mainloop: C[128x128] = A[128x1024] @ B[128x1024]^T.
// 8 warps 2x4 (warp tile 64x32). Fragment-order smem, cp.async 3-stage.
// ============================================================================
#define G16_STG 16384
__device__ __forceinline__ void gemm16_1024(
    const __half* __restrict__ A, const __half* __restrict__ Bm,
    char* dsm, u32 sb, float (&c)[4][4][4])
{
    const int tid = threadIdx.x, lane = tid & 31, wid = tid >> 5;
    const int wm = wid >> 2, wn = wid & 3;

    u32 sA[2]; const __half* gA[2];
    #pragma unroll
    for (int p = 0; p < 2; ++p) {
        int id = tid + p * 256;
        int row = id >> 2, k8 = (id & 3) * 8;
        int f = ((row >> 4) * 2 + (k8 >> 4)) * 4 + ((row >> 3) & 1) + (((k8 >> 3) & 1) << 1);
        sA[p] = sb + (u32)((f * 32 + (row & 7) * 4) * 4);
        gA[p] = A + (size_t)row * 1024 + k8;
    }
    u32 sB[2]; const __half* gB[2];
    #pragma unroll
    for (int p = 0; p < 2; ++p) {
        int id = tid + p * 256;
        int n = id >> 2, k8 = (id & 3) * 8;
        int f = ((n >> 3) * 2 + (k8 >> 4)) * 2 + ((k8 >> 3) & 1);
        sB[p] = sb + 8192 + (u32)((f * 32 + (n & 7) * 4) * 4);
        gB[p] = Bm + (size_t)n * 1024 + k8;
    }
    auto load = [&](int s) {
        u32 off = (u32)((s % 3) * G16_STG);
        int k0 = s << 5;
        #pragma unroll
        for (int p = 0; p < 2; ++p) CP16(sA[p] + off, gA[p] + k0);
        #pragma unroll
        for (int p = 0; p < 2; ++p) CP16(sB[p] + off, gB[p] + k0);
        CPC;
    };
    load(0); load(1);

    for (int ch = 0; ch < 32; ++ch) {
        CPW(1);
        __syncthreads();
        if (ch + 2 < 32) load(ch + 2); else CPC;
        const char* st = dsm + (ch % 3) * G16_STG;
        #pragma unroll
        for (int kt = 0; kt < 2; ++kt) {
            u32 br[4][2];
            #pragma unroll
            for (int nt = 0; nt < 4; ++nt)
                #pragma unroll
                for (int r = 0; r < 2; ++r)
                    br[nt][r] = *(const u32*)(st + 8192
                        + ((((wn * 4 + nt) * 2 + kt) * 2 + r) * 32 + lane) * 4);
            #pragma unroll
            for (int mt = 0; mt < 4; ++mt) {
                u32 ar[4];
                #pragma unroll
                for (int r = 0; r < 4; ++r)
                    ar[r] = *(const u32*)(st
                        + ((((wm * 4 + mt) * 2 + kt) * 4 + r) * 32 + lane) * 4);
                #pragma unroll
                for (int nt = 0; nt < 4; ++nt)
                    MMA_F16(c[mt][nt], ar[0],ar[1],ar[2],ar[3], br[nt][0],br[nt][1]);
            }
        }
    }
}

// ============================================================================
// Prep kernels
// ============================================================================
__global__ __launch_bounds__(256) void k_xh(const float* __restrict__ x)
{
    size_t base = ((size_t)blockIdx.x * 256 + threadIdx.x) * 8;
    float4 v0 = *(const float4*)(x + base);
    float4 v1 = *(const float4*)(x + base + 4);
    __half2 h0 = __floats2half2_rn(v0.x, v0.y);
    __half2 h1 = __floats2half2_rn(v0.z, v0.w);
    __half2 h2 = __floats2half2_rn(v1.x, v1.y);
    __half2 h3 = __floats2half2_rn(v1.z, v1.w);
    *(uint4*)(g_xh + base) = make_uint4(*(u32*)&h0, *(u32*)&h1, *(u32*)&h2, *(u32*)&h3);
}

__global__ __launch_bounds__(256) void k_wqh(const float* __restrict__ w)
{
    __shared__ float tile[32][33];
    int bx = blockIdx.x * 32, by = blockIdx.y * 32;   // bx: n(3072), by: k(1024)
    int tx = threadIdx.x, ty = threadIdx.y;
    float sc = (bx < 1024) ? SCALE_ : 1.0f;
    #pragma unroll
    for (int i = 0; i < 32; i += 8)
        tile[ty + i][tx] = w[(size_t)(by + ty + i) * 3072 + bx + tx];
    __syncthreads();
    #pragma unroll
    for (int i = 0; i < 32; i += 8)
        g_wqh[(size_t)(bx + ty + i) * 1024 + by + tx] = __float2half(tile[tx][ty + i] * sc);
}

__global__ __launch_bounds__(256) void k_woutT(const float* __restrict__ w)
{
    __shared__ float tile[32][33];
    int bx = blockIdx.x * 32, by = blockIdx.y * 32;
    int tx = threadIdx.x, ty = threadIdx.y;
    #pragma unroll
    for (int i = 0; i < 32; i += 8)
        tile[ty + i][tx] = w[(size_t)(by + ty + i) * D_ + bx + tx];
    __syncthreads();
    #pragma unroll
    for (int i = 0; i < 32; i += 8)
        g_woutTh[(size_t)(bx + ty + i) * D_ + by + tx] = __float2half(tile[tx][ty + i]);
}

__global__ void k_vT()
{
    __shared__ __half tile[32][33];
    int bh = blockIdx.z, s0 = blockIdx.x * 32, d0 = blockIdx.y * 32;
    int tx = threadIdx.x, ty = threadIdx.y;
    const __half* src = g_vh + (size_t)bh * S_ * 64;
    __half* dst = g_vTh + (size_t)bh * 64 * S_;
    #pragma unroll
    for (int i = 0; i < 32; i += 8)
        tile[ty + i][tx] = src[(size_t)(s0 + ty + i) * 64 + d0 + tx];
    __syncthreads();
    #pragma unroll
    for (int i = 0; i < 32; i += 8)
        dst[(size_t)(d0 + ty + i) * S_ + s0 + tx] = tile[tx][ty + i];
}

// ============================================================================
// Kernel 1: QKV projection (fp16 1x) -> scatter q/k/v fp16
// ============================================================================
__global__ __launch_bounds__(256, 2) void k_qkv(const float* __restrict__ bias)
{
    extern __shared__ __align__(16) char dsm[];
    u32 sb = smem_u32(dsm);
    const int row0 = blockIdx.y * 128, col0 = blockIdx.x * 128;

    float c[4][4][4]; ZERO_C3(c, 4);
    gemm16_1024(g_xh + (size_t)row0 * 1024, g_wqh + (size_t)col0 * 1024, dsm, sb, c);

    const int lane = threadIdx.x & 31, wid = threadIdx.x >> 5;
    const int wm = wid >> 2, wn = wid & 3, g = lane >> 2, t = lane & 3;
    const int three = col0 >> 10;
    const float bsc = (three == 0) ? SCALE_ : 1.0f;
    #pragma unroll
    for (int nt = 0; nt < 4; ++nt) {
        int gcol = col0 + wn * 32 + nt * 8 + t * 2;
        float b0 = __ldg(bias + gcol) * bsc, b1 = __ldg(bias + gcol + 1) * bsc;
        int h = (gcol >> 6) & 15, dh = gcol & 63;
        __half* dst = (three == 0) ? g_qh : (three == 1) ? g_kh : g_vh;
        #pragma unroll
        for (int mt = 0; mt < 4; ++mt)
            #pragma unroll
            for (int hh = 0; hh < 2; ++hh) {
                int gm = row0 + wm * 64 + mt * 16 + hh * 8 + g;
                int b = gm >> 11, s = gm & 2047;
                size_t base = ((size_t)(b * 16 + h) * S_ + s) * 64 + dh;
                __half2 hv = __floats2half2_rn(c[mt][nt][hh * 2] + b0,
                                               c[mt][nt][hh * 2 + 1] + b1);
                *(u32*)(dst + base) = *(u32*)&hv;
            }
    }
}

// ============================================================================
// Kernel 2: fused flash attention, all fp16 1x. Q fragments in registers.
// CTA = 128 q-rows x 1 head; 32 KV tiles of 64; 4-stage cp.async.
// ============================================================================
#define ATQ    16384
#define ATSTG  16384   // K 8KB + V 8KB
__global__ __launch_bounds__(256, 2) void k_attn()
{
    extern __shared__ __align__(16) char dsm[];
    u32 sb = smem_u32(dsm);
    const int tid = threadIdx.x, lane = tid & 31, wid = tid >> 5;
    const int g = lane >> 2, t = lane & 3;
    const int bh = blockIdx.y, row0 = blockIdx.x * 128;

    // KV producer maps (K: 64 keys x 64 dh; V^T: 64 dh x 64 keys)
    u32 kOff[2]; const __half* kG[2];
    #pragma unroll
    for (int p = 0; p < 2; ++p) {
        int id = tid + p * 256;
        int n = id >> 3, cc = id & 7;
        kOff[p] = (u32)(((((n >> 3) * 4 + (cc >> 1)) * 2 + (cc & 1)) * 128) + (n & 7) * 16);
        kG[p] = g_kh + ((size_t)bh * S_ + n) * 64 + cc * 8;
    }
    u32 vOff[2]; const __half* vG[2];
    #pragma unroll
    for (int p = 0; p < 2; ++p) {
        int id = tid + p * 256;
        int n = id >> 3, cc = id & 7;
        vOff[p] = (u32)(8192 + ((((n >> 3) * 4 + (cc >> 1)) * 2 + (cc & 1)) * 128) + (n & 7) * 16);
        vG[p] = g_vTh + ((size_t)bh * 64 + n) * S_ + cc * 8;
    }
    auto loadKV = [&](int it) {
        u32 so = sb + ATQ + (u32)((it & 3) * ATSTG);
        int kv0 = it * 64;
        #pragma unroll
        for (int p = 0; p < 2; ++p) CP16(so + kOff[p], kG[p] + (size_t)kv0 * 64);
        #pragma unroll
        for (int p = 0; p < 2; ++p) CP16(so + vOff[p], vG[p] + kv0);
        CPC;
    };
    loadKV(0); loadKV(1); loadKV(2);

    // Stage Q (plain loads), then lift fragments into registers
    const __half* qg = g_qh + ((size_t)bh * S_ + row0) * 64;
    #pragma unroll
    for (int p = 0; p < 4; ++p) {
        int id = tid + p * 256;
        int row = id >> 3, cc = id & 7;
        uint4 v = *(const uint4*)(qg + (size_t)row * 64 + cc * 8);
        u32 off = (u32)(((((row >> 4) * 4 + (cc >> 1)) * 4
                 + ((row >> 3) & 1) + 2 * (cc & 1)) * 128) + (row & 7) * 16);
        *(uint4*)(dsm + off) = v;
    }
    __syncthreads();
    u32 qf[4][4];
    #pragma unroll
    for (int kt = 0; kt < 4; ++kt)
        #pragma unroll
        for (int r = 0; r < 4; ++r)
            qf[kt][r] = *(const u32*)(dsm + (((wid * 4 + kt) * 4 + r) * 128) + lane * 4);

    float co[8][4]; ZERO_C2(co, 8);
    float ls0 = 0.f, ls1 = 0.f;

    for (int it = 0; it < 32; ++it) {
        CPW(2);
        __syncthreads();
        if (it + 3 < 32) loadKV(it + 3); else CPC;
        const char* stK = dsm + ATQ + (it & 3) * ATSTG;
        const char* stV = stK + 8192;

        // S = Q K^T
        float cs[8][4]; ZERO_C2(cs, 8);
        #pragma unroll
        for (int kt = 0; kt < 4; ++kt)
            #pragma unroll
            for (int nt = 0; nt < 8; ++nt) {
                u32 b0 = *(const u32*)(stK + (((nt * 4 + kt) * 2 + 0) * 128) + lane * 4);
                u32 b1 = *(const u32*)(stK + (((nt * 4 + kt) * 2 + 1) * 128) + lane * 4);
                MMA_F16(cs[nt], qf[kt][0], qf[kt][1], qf[kt][2], qf[kt][3], b0, b1);
            }

        // exp + pack into PV A-fragments
        u32 ap[4][4];
        #pragma unroll
        for (int nt = 0; nt < 8; ++nt) {
            float e0 = __expf(cs[nt][0]);
            float e1 = __expf(cs[nt][1]);
            float e2 = __expf(cs[nt][2]);
            float e3 = __expf(cs[nt][3]);
            ls0 += e0 + e1; ls1 += e2 + e3;
            __half2 p01 = __floats2half2_rn(e0, e1);
            __half2 p23 = __floats2half2_rn(e2, e3);
            ap[nt >> 1][(nt & 1) * 2 + 0] = *(u32*)&p01;
            ap[nt >> 1][(nt & 1) * 2 + 1] = *(u32*)&p23;
        }

        // O += P V
        #pragma unroll
        for (int kt2 = 0; kt2 < 4; ++kt2)
            #pragma unroll
            for (int nt = 0; nt < 8; ++nt) {
                u32 v0 = *(const u32*)(stV + (((nt * 4 + kt2) * 2 + 0) * 128) + lane * 4);
                u32 v1 = *(const u32*)(stV + (((nt * 4 + kt2) * 2 + 1) * 128) + lane * 4);
                MMA_F16(co[nt], ap[kt2][0], ap[kt2][1], ap[kt2][2], ap[kt2][3], v0, v1);
            }
    }

    // normalize and write
    ls0 += __shfl_xor_sync(0xffffffffu, ls0, 1);
    ls0 += __shfl_xor_sync(0xffffffffu, ls0, 2);
    ls1 += __shfl_xor_sync(0xffffffffu, ls1, 1);
    ls1 += __shfl_xor_sync(0xffffffffu, ls1, 2);
    float inv0 = 1.0f / ls0, inv1 = 1.0f / ls1;

    const int b = bh >> 4, h = bh & 15;
    int r0 = row0 + wid * 16 + g;
    __half* o0 = g_aoh + ((size_t)b * S_ + r0) * D_ + h * 64;
    __half* o1 = o0 + (size_t)8 * D_;
    #pragma unroll
    for (int nt = 0; nt < 8; ++nt) {
        int dh = nt * 8 + t * 2;
        __half2 w0 = __floats2half2_rn(co[nt][0] * inv0, co[nt][1] * inv0);
        __half2 w1 = __floats2half2_rn(co[nt][2] * inv1, co[nt][3] * inv1);
        *(u32*)(o0 + dh) = *(u32*)&w0;
        *(u32*)(o1 + dh) = *(u32*)&w1;
    }
}

// ============================================================================
// Kernel 3: output projection (fp16 1x)
// ============================================================================
__global__ __launch_bounds__(256, 2) void k_out(
    const float* __restrict__ bias, float* __restrict__ out)
{
    extern __shared__ __align__(16) char dsm[];
    u32 sb = smem_u32(dsm);
    const int row0 = blockIdx.y * 128, col0 = blockIdx.x * 128;

    float c[4][4][4]; ZERO_C3(c, 4);
    gemm16_1024(g_aoh + (size_t)row0 * D_, g_woutTh + (size_t)col0 * D_, dsm, sb, c);

    const int lane = threadIdx.x & 31, wid = threadIdx.x >> 5;
    const int wm = wid >> 2, wn = wid & 3, g = lane >> 2, t = lane & 3;
    #pragma unroll
    for (int nt = 0; nt < 4; ++nt) {
        int gcol = col0 + wn * 32 + nt * 8 + t * 2;
        float b0 = __ldg(bias + gcol), b1 = __ldg(bias + gcol + 1);
        #pragma unroll
        for (int mt = 0; mt < 4; ++mt)
            #pragma unroll
            for (int hh = 0; hh < 2; ++hh) {
                int gm = row0 + wm * 64 + mt * 16 + hh * 8 + g;
                *(float2*)(out + (size_t)gm * D_ + gcol) =
                    make_float2(c[mt][nt][hh * 2] + b0, c[mt][nt][hh * 2 + 1] + b1);
            }
    }
}

// ---------------------------------------------------------------------------
#define DYN_G16 49152
#define DYN_ATT (ATQ + 4 * ATSTG)   // 81920

extern "C" void kernel_launch(void* const* d_in, const int* in_sizes, int n_in,
                              void* d_out, int out_size)
{
    (void)in_sizes; (void)n_in; (void)out_size;
    const float* x     = (const float*)d_in[0];
    const float* w_qkv = (const float*)d_in[1];
    const float* b_qkv = (const float*)d_in[2];
    const float* w_out = (const float*)d_in[3];
    const float* b_out = (const float*)d_in[4];
    float* out = (float*)d_out;

    cudaFuncSetAttribute(k_qkv,  cudaFuncAttributeMaxDynamicSharedMemorySize, DYN_G16);
    cudaFuncSetAttribute(k_attn, cudaFuncAttributeMaxDynamicSharedMemorySize, DYN_ATT);
    cudaFuncSetAttribute(k_out,  cudaFuncAttributeMaxDynamicSharedMemorySize, DYN_G16);

    k_xh<<<4096, 256>>>(x);
    k_wqh<<<dim3(96, 32), dim3(32, 8)>>>(w_qkv);
    k_woutT<<<dim3(32, 32), dim3(32, 8)>>>(w_out);

    k_qkv<<<dim3(24, 64), 256, DYN_G16>>>(b_qkv);
    k_vT<<<dim3(64, 2, 64), dim3(32, 8)>>>();
    k_attn<<<dim3(16, 64), 256, DYN_ATT>>>();
    k_out<<<dim3(8, 64), 256, DYN_G16>>>(b_out, out);
}

// round 9
// speedup vs baseline: 18.0336x; 1.6459x over previous
#include <cuda_runtime.h>
#include <cuda_fp16.h>
#include <math.h>

typedef unsigned int u32;

#define D_ 1024
#define S_ 2048
#define SCALE_ 0.125f

// ---------------- device-global scratch ------------------------------------
__device__ __half g_xh   [(size_t)8192 * 1024];   // x fp16 [tok][1024]
__device__ __half g_wqh  [(size_t)3072 * 1024];   // w_qkv^T fp16 (q rows pre-scaled)
__device__ __half g_qh   [(size_t)64 * S_ * 64];  // [bh][s][dh] (scaled)
__device__ __half g_kh   [(size_t)64 * S_ * 64];
__device__ __half g_vTh  [(size_t)64 * 64 * S_];  // [bh][dh][s]
__device__ __half g_aoh  [(size_t)8192 * D_];
__device__ __half g_woutTh[(size_t)D_ * D_];

// ---------------- helpers ---------------------------------------------------
__device__ __forceinline__ u32 smem_u32(const void* p) {
    u32 a;
    asm("{ .reg .u64 t; cvta.to.shared.u64 t, %1; cvt.u32.u64 %0, t; }" : "=r"(a) : "l"(p));
    return a;
}
#define CP16(s, g) asm volatile("cp.async.cg.shared.global [%0], [%1], 16;" :: "r"(s), "l"(g))
#define CPC        asm volatile("cp.async.commit_group;")
#define CPW(n)     asm volatile("cp.async.wait_group %0;" :: "n"(n))

#define LDSM4(r0, r1, r2, r3, addr) asm volatile( \
    "ldmatrix.sync.aligned.m8n8.x4.shared.b16 {%0,%1,%2,%3}, [%4];" \
    : "=r"(r0), "=r"(r1), "=r"(r2), "=r"(r3) : "r"(addr))

#define MMA_F16(c, a0,a1,a2,a3, b0,b1) asm volatile( \
    "mma.sync.aligned.m16n8k16.row.col.f32.f16.f16.f32 " \
    "{%0,%1,%2,%3},{%4,%5,%6,%7},{%8,%9},{%0,%1,%2,%3};" \
    : "+f"((c)[0]), "+f"((c)[1]), "+f"((c)[2]), "+f"((c)[3]) \
    : "r"(a0), "r"(a1), "r"(a2), "r"(a3), "r"(b0), "r"(b1))

#define ZERO_C3(c, MT) { _Pragma("unroll") for (int m = 0; m < MT; ++m) \
    _Pragma("unroll") for (int n = 0; n < 4; ++n) \
    _Pragma("unroll") for (int r = 0; r < 4; ++r) (c)[m][n][r] = 0.f; }

#define ZERO_C2(c, NT) { _Pragma("unroll") for (int n = 0; n < NT; ++n) \
    _Pragma("unroll") for (int r = 0; r < 4; ++r) (c)[n][r] = 0.f; }

// ============================================================================
// fp16 GEMM mainloop, ldmatrix consumer: C[128x128] = A[128x1024] @ B^T.
// Tiles: row-major, 64B rows (32 halves/chunk of k), swizzle c ^= (row>>1)&3.
// 4-stage cp.async. 8 warps 2x4.
// ============================================================================
#define GSTG 16384
__device__ __forceinline__ void gemm16_1024(
    const __half* __restrict__ A, const __half* __restrict__ Bm,
    char* dsm, u32 sb, float (&c)[4][4][4])
{
    const int tid = threadIdx.x, lane = tid & 31, wid = tid >> 5;
    const int wm = wid >> 2, wn = wid & 3;
    const int li = lane & 7, mi = lane >> 3, s3 = li >> 1;

    // producers: A/B each 128 rows x 4 chunks -> 2 chunks/thread each
    u32 sA[2]; const __half* gA[2];
    u32 sB[2]; const __half* gB[2];
    #pragma unroll
    for (int p = 0; p < 2; ++p) {
        int id = tid + p * 256;
        int row = id >> 2, cc = id & 3;
        u32 sw = (u32)(row * 64 + ((cc ^ ((row >> 1) & 3)) << 4));
        sA[p] = sb + sw;
        gA[p] = A + (size_t)row * 1024 + cc * 8;
        sB[p] = sb + 8192 + sw;
        gB[p] = Bm + (size_t)row * 1024 + cc * 8;
    }
    auto load = [&](int s) {
        u32 off = (u32)((s & 3) * GSTG);
        int k0 = s << 5;
        #pragma unroll
        for (int p = 0; p < 2; ++p) CP16(sA[p] + off, gA[p] + k0);
        #pragma unroll
        for (int p = 0; p < 2; ++p) CP16(sB[p] + off, gB[p] + k0);
        CPC;
    };
    load(0); load(1); load(2);

    // consumer address bases (lane-constant)
    const u32 aBase = (u32)((wm * 64 + ((mi & 1) << 3) + li) * 64);
    const u32 xA0 = (u32)((((0 << 1) | (mi >> 1)) ^ s3) << 4);
    const u32 xA1 = (u32)((((1 << 1) | (mi >> 1)) ^ s3) << 4);
    const u32 bBase = (u32)(8192 + (wn * 32 + li) * 64 + ((mi ^ s3) << 4));

    for (int ch = 0; ch < 32; ++ch) {
        CPW(2);
        __syncthreads();
        if (ch + 3 < 32) load(ch + 3); else CPC;
        u32 st = sb + (u32)((ch & 3) * GSTG);

        u32 bb[4][4];
        #pragma unroll
        for (int nt = 0; nt < 4; ++nt)
            LDSM4(bb[nt][0], bb[nt][1], bb[nt][2], bb[nt][3],
                  st + bBase + nt * 512);
        #pragma unroll
        for (int mt = 0; mt < 4; ++mt) {
            u32 aadr = st + aBase + mt * 1024;
            u32 a0, a1, a2, a3;
            LDSM4(a0, a1, a2, a3, aadr + xA0);
            #pragma unroll
            for (int nt = 0; nt < 4; ++nt)
                MMA_F16(c[mt][nt], a0, a1, a2, a3, bb[nt][0], bb[nt][1]);
            LDSM4(a0, a1, a2, a3, aadr + xA1);
            #pragma unroll
            for (int nt = 0; nt < 4; ++nt)
                MMA_F16(c[mt][nt], a0, a1, a2, a3, bb[nt][2], bb[nt][3]);
        }
    }
}

// ============================================================================
// Prep kernels
// ============================================================================
__global__ __launch_bounds__(256) void k_xh(const float* __restrict__ x)
{
    size_t base = ((size_t)blockIdx.x * 256 + threadIdx.x) * 8;
    float4 v0 = *(const float4*)(x + base);
    float4 v1 = *(const float4*)(x + base + 4);
    __half2 h0 = __floats2half2_rn(v0.x, v0.y);
    __half2 h1 = __floats2half2_rn(v0.z, v0.w);
    __half2 h2 = __floats2half2_rn(v1.x, v1.y);
    __half2 h3 = __floats2half2_rn(v1.z, v1.w);
    *(uint4*)(g_xh + base) = make_uint4(*(u32*)&h0, *(u32*)&h1, *(u32*)&h2, *(u32*)&h3);
}

__global__ __launch_bounds__(256) void k_wqh(const float* __restrict__ w)
{
    __shared__ float tile[32][33];
    int bx = blockIdx.x * 32, by = blockIdx.y * 32;
    int tx = threadIdx.x, ty = threadIdx.y;
    float sc = (bx < 1024) ? SCALE_ : 1.0f;
    #pragma unroll
    for (int i = 0; i < 32; i += 8)
        tile[ty + i][tx] = w[(size_t)(by + ty + i) * 3072 + bx + tx];
    __syncthreads();
    #pragma unroll
    for (int i = 0; i < 32; i += 8)
        g_wqh[(size_t)(bx + ty + i) * 1024 + by + tx] = __float2half(tile[tx][ty + i] * sc);
}

__global__ __launch_bounds__(256) void k_woutT(const float* __restrict__ w)
{
    __shared__ float tile[32][33];
    int bx = blockIdx.x * 32, by = blockIdx.y * 32;
    int tx = threadIdx.x, ty = threadIdx.y;
    #pragma unroll
    for (int i = 0; i < 32; i += 8)
        tile[ty + i][tx] = w[(size_t)(by + ty + i) * D_ + bx + tx];
    __syncthreads();
    #pragma unroll
    for (int i = 0; i < 32; i += 8)
        g_woutTh[(size_t)(bx + ty + i) * D_ + by + tx] = __float2half(tile[tx][ty + i]);
}

// ============================================================================
// Kernel 1: QKV projection (fp16 1x). q/k stored [bh][s][dh]; V written
// transposed directly into g_vTh.
// ============================================================================
__global__ __launch_bounds__(256, 2) void k_qkv(const float* __restrict__ bias)
{
    extern __shared__ __align__(16) char dsm[];
    u32 sb = smem_u32(dsm);
    const int row0 = blockIdx.y * 128, col0 = blockIdx.x * 128;

    float c[4][4][4]; ZERO_C3(c, 4);
    gemm16_1024(g_xh + (size_t)row0 * 1024, g_wqh + (size_t)col0 * 1024, dsm, sb, c);

    const int lane = threadIdx.x & 31, wid = threadIdx.x >> 5;
    const int wm = wid >> 2, wn = wid & 3, g = lane >> 2, t = lane & 3;
    const int three = col0 >> 10;
    const float bsc = (three == 0) ? SCALE_ : 1.0f;
    #pragma unroll
    for (int nt = 0; nt < 4; ++nt) {
        int gcol = col0 + wn * 32 + nt * 8 + t * 2;
        float b0 = __ldg(bias + gcol) * bsc, b1 = __ldg(bias + gcol + 1) * bsc;
        int h = (gcol >> 6) & 15, dh = gcol & 63;
        #pragma unroll
        for (int mt = 0; mt < 4; ++mt)
            #pragma unroll
            for (int hh = 0; hh < 2; ++hh) {
                int gm = row0 + wm * 64 + mt * 16 + hh * 8 + g;
                int b = gm >> 11, s = gm & 2047;
                float v0 = c[mt][nt][hh * 2] + b0, v1 = c[mt][nt][hh * 2 + 1] + b1;
                if (three == 2) {
                    size_t vb = ((size_t)(b * 16 + h) * 64 + dh) * S_ + s;
                    g_vTh[vb]      = __float2half(v0);
                    g_vTh[vb + S_] = __float2half(v1);
                } else {
                    __half* dst = (three == 0) ? g_qh : g_kh;
                    size_t base = ((size_t)(b * 16 + h) * S_ + s) * 64 + dh;
                    __half2 hv = __floats2half2_rn(v0, v1);
                    *(u32*)(dst + base) = *(u32*)&hv;
                }
            }
    }
}

// ============================================================================
// Kernel 2: fused flash attention, ldmatrix consumers.
// CTA = 128 q-rows x 1 head; KV tiles of 64; 4-stage cp.async; Q in registers.
// Tiles 128B rows, swizzle c ^= row&7.
// ============================================================================
#define ATQ   16384
#define ATSTG 16384
__global__ __launch_bounds__(256, 2) void k_attn()
{
    extern __shared__ __align__(16) char dsm[];
    u32 sb = smem_u32(dsm);
    const int tid = threadIdx.x, lane = tid & 31, wid = tid >> 5;
    const int g = lane >> 2, t = lane & 3;
    const int li = lane & 7, mi = lane >> 3;
    const int bh = blockIdx.y, row0 = blockIdx.x * 128;

    // ---- Q producer (group 0): 128 rows x 8 chunks
    {
        const __half* qg = g_qh + ((size_t)bh * S_ + row0) * 64;
        #pragma unroll
        for (int p = 0; p < 4; ++p) {
            int id = tid + p * 256;
            int row = id >> 3, cc = id & 7;
            u32 off = (u32)(row * 128 + ((cc ^ (row & 7)) << 4));
            CP16(sb + off, qg + (size_t)row * 64 + cc * 8);
        }
        CPC;
    }

    // ---- KV producers
    u32 kOff[2], vOff[2];
    const __half* kG[2];
    const __half* vG[2];
    #pragma unroll
    for (int p = 0; p < 2; ++p) {
        int id = tid + p * 256;
        int row = id >> 3, cc = id & 7;
        u32 sw = (u32)(row * 128 + ((cc ^ (row & 7)) << 4));
        kOff[p] = sw;
        kG[p] = g_kh + ((size_t)bh * S_ + row) * 64 + cc * 8;
        vOff[p] = 8192 + sw;
        vG[p] = g_vTh + ((size_t)bh * 64 + row) * S_ + cc * 8;
    }
    auto loadKV = [&](int it) {
        u32 so = sb + ATQ + (u32)((it & 3) * ATSTG);
        int kv0 = it * 64;
        #pragma unroll
        for (int p = 0; p < 2; ++p) CP16(so + kOff[p], kG[p] + (size_t)kv0 * 64);
        #pragma unroll
        for (int p = 0; p < 2; ++p) CP16(so + vOff[p], vG[p] + kv0);
        CPC;
    };
    loadKV(0); loadKV(1); loadKV(2);

    // ---- Q fragments -> registers (after Q group completes)
    CPW(3);
    __syncthreads();
    u32 qf[4][4];
    {
        u32 qBase = sb + (u32)((wid * 16 + ((mi & 1) << 3) + li) * 128);
        #pragma unroll
        for (int kt = 0; kt < 4; ++kt) {
            u32 x = (u32)(((((kt << 1) | (mi >> 1))) ^ li) << 4);
            LDSM4(qf[kt][0], qf[kt][1], qf[kt][2], qf[kt][3], qBase + x);
        }
    }

    // consumer lane-constant bases (K and V share geometry)
    const u32 fragBase = (u32)(li * 128 + ((mi ^ li) << 4));   // + nt*1024; ^64 for hi

    float co[8][4]; ZERO_C2(co, 8);
    float ls0 = 0.f, ls1 = 0.f;

    for (int it = 0; it < 32; ++it) {
        CPW(2);
        __syncthreads();
        if (it + 3 < 32) loadKV(it + 3); else CPC;
        u32 stK = sb + ATQ + (u32)((it & 3) * ATSTG);
        u32 stV = stK + 8192;

        // S = Q K^T
        float cs[8][4]; ZERO_C2(cs, 8);
        #pragma unroll
        for (int nt = 0; nt < 8; ++nt) {
            u32 k0, k1, k2, k3, k4, k5, k6, k7;
            u32 adr = stK + fragBase + nt * 1024;
            LDSM4(k0, k1, k2, k3, adr);
            LDSM4(k4, k5, k6, k7, adr ^ 64);
            MMA_F16(cs[nt], qf[0][0], qf[0][1], qf[0][2], qf[0][3], k0, k1);
            MMA_F16(cs[nt], qf[1][0], qf[1][1], qf[1][2], qf[1][3], k2, k3);
            MMA_F16(cs[nt], qf[2][0], qf[2][1], qf[2][2], qf[2][3], k4, k5);
            MMA_F16(cs[nt], qf[3][0], qf[3][1], qf[3][2], qf[3][3], k6, k7);
        }

        // exp + pack into PV A-fragments
        u32 ap[4][4];
        #pragma unroll
        for (int nt = 0; nt < 8; ++nt) {
            float e0 = __expf(cs[nt][0]);
            float e1 = __expf(cs[nt][1]);
            float e2 = __expf(cs[nt][2]);
            float e3 = __expf(cs[nt][3]);
            ls0 += e0 + e1; ls1 += e2 + e3;
            __half2 p01 = __floats2half2_rn(e0, e1);
            __half2 p23 = __floats2half2_rn(e2, e3);
            ap[nt >> 1][(nt & 1) * 2 + 0] = *(u32*)&p01;
            ap[nt >> 1][(nt & 1) * 2 + 1] = *(u32*)&p23;
        }

        // O += P V
        #pragma unroll
        for (int nt = 0; nt < 8; ++nt) {
            u32 v0, v1, v2, v3, v4, v5, v6, v7;
            u32 adr = stV + fragBase + nt * 1024;
            LDSM4(v0, v1, v2, v3, adr);
            LDSM4(v4, v5, v6, v7, adr ^ 64);
            MMA_F16(co[nt], ap[0][0], ap[0][1], ap[0][2], ap[0][3], v0, v1);
            MMA_F16(co[nt], ap[1][0], ap[1][1], ap[1][2], ap[1][3], v2, v3);
            MMA_F16(co[nt], ap[2][0], ap[2][1], ap[2][2], ap[2][3], v4, v5);
            MMA_F16(co[nt], ap[3][0], ap[3][1], ap[3][2], ap[3][3], v6, v7);
        }
    }

    // normalize and write
    ls0 += __shfl_xor_sync(0xffffffffu, ls0, 1);
    ls0 += __shfl_xor_sync(0xffffffffu, ls0, 2);
    ls1 += __shfl_xor_sync(0xffffffffu, ls1, 1);
    ls1 += __shfl_xor_sync(0xffffffffu, ls1, 2);
    float inv0 = 1.0f / ls0, inv1 = 1.0f / ls1;

    const int b = bh >> 4, h = bh & 15;
    int r0 = row0 + wid * 16 + g;
    __half* o0 = g_aoh + ((size_t)b * S_ + r0) * D_ + h * 64;
    __half* o1 = o0 + (size_t)8 * D_;
    #pragma unroll
    for (int nt = 0; nt < 8; ++nt) {
        int dh = nt * 8 + t * 2;
        __half2 w0 = __floats2half2_rn(co[nt][0] * inv0, co[nt][1] * inv0);
        __half2 w1 = __floats2half2_rn(co[nt][2] * inv1, co[nt][3] * inv1);
        *(u32*)(o0 + dh) = *(u32*)&w0;
        *(u32*)(o1 + dh) = *(u32*)&w1;
    }
}

// ============================================================================
// Kernel 3: output projection (fp16 1x)
// ============================================================================
__global__ __launch_bounds__(256, 2) void k_out(
    const float* __restrict__ bias, float* __restrict__ out)
{
    extern __shared__ __align__(16) char dsm[];
    u32 sb = smem_u32(dsm);
    const int row0 = blockIdx.y * 128, col0 = blockIdx.x * 128;

    float c[4][4][4]; ZERO_C3(c, 4);
    gemm16_1024(g_aoh + (size_t)row0 * D_, g_woutTh + (size_t)col0 * D_, dsm, sb, c);

    const int lane = threadIdx.x & 31, wid = threadIdx.x >> 5;
    const int wm = wid >> 2, wn = wid & 3, g = lane >> 2, t = lane & 3;
    #pragma unroll
    for (int nt = 0; nt < 4; ++nt) {
        int gcol = col0 + wn * 32 + nt * 8 + t * 2;
        float b0 = __ldg(bias + gcol), b1 = __ldg(bias + gcol + 1);
        #pragma unroll
        for (int mt = 0; mt < 4; ++mt)
            #pragma unroll
            for (int hh = 0; hh < 2; ++hh) {
                int gm = row0 + wm * 64 + mt * 16 + hh * 8 + g;
                *(float2*)(out + (size_t)gm * D_ + gcol) =
                    make_float2(c[mt][nt][hh * 2] + b0, c[mt][nt][hh * 2 + 1] + b1);
            }
    }
}

// ---------------------------------------------------------------------------
#define DYN_G16 (4 * GSTG)          // 65536
#define DYN_ATT (ATQ + 4 * ATSTG)   // 81920

extern "C" void kernel_launch(void* const* d_in, const int* in_sizes, int n_in,
                              void* d_out, int out_size)
{
    (void)in_sizes; (void)n_in; (void)out_size;
    const float* x     = (const float*)d_in[0];
    const float* w_qkv = (const float*)d_in[1];
    const float* b_qkv = (const float*)d_in[2];
    const float* w_out = (const float*)d_in[3];
    const float* b_out = (const float*)d_in[4];
    float* out = (float*)d_out;

    cudaFuncSetAttribute(k_qkv,  cudaFuncAttributeMaxDynamicSharedMemorySize, DYN_G16);
    cudaFuncSetAttribute(k_attn, cudaFuncAttributeMaxDynamicSharedMemorySize, DYN_ATT);
    cudaFuncSetAttribute(k_out,  cudaFuncAttributeMaxDynamicSharedMemorySize, DYN_G16);

    k_xh<<<4096, 256>>>(x);
    k_wqh<<<dim3(96, 32), dim3(32, 8)>>>(w_qkv);
    k_woutT<<<dim3(32, 32), dim3(32, 8)>>>(w_out);

    k_qkv<<<dim3(24, 64), 256, DYN_G16>>>(b_qkv);
    k_attn<<<dim3(16, 64), 256, DYN_ATT>>>();
    k_out<<<dim3(8, 64), 256, DYN_G16>>>(b_out, out);
}

// round 10
// speedup vs baseline: 19.1705x; 1.0630x over previous
#include <cuda_runtime.h>
#include <cuda_fp16.h>
#include <math.h>

typedef unsigned int u32;

#define D_ 1024
#define S_ 2048
#define SCALE_ 0.125f
#define LOG2E_ 1.4426950408889634f

// ---------------- device-global scratch ------------------------------------
__device__ __half g_xh   [(size_t)8192 * 1024];
__device__ __half g_wqh  [(size_t)3072 * 1024];   // w_qkv^T fp16 (q rows pre-scaled by SCALE*LOG2E)
__device__ __half g_qh   [(size_t)64 * S_ * 64];  // [bh][s][dh] (scaled, log2 domain)
__device__ __half g_kh   [(size_t)64 * S_ * 64];
__device__ __half g_vTh  [(size_t)64 * 64 * S_];  // [bh][dh][s]
__device__ __half g_aoh  [(size_t)8192 * D_];
__device__ __half g_woutTh[(size_t)D_ * D_];

// ---------------- helpers ---------------------------------------------------
__device__ __forceinline__ u32 smem_u32(const void* p) {
    u32 a;
    asm("{ .reg .u64 t; cvta.to.shared.u64 t, %1; cvt.u32.u64 %0, t; }" : "=r"(a) : "l"(p));
    return a;
}
#define CP16(s, g) asm volatile("cp.async.cg.shared.global [%0], [%1], 16;" :: "r"(s), "l"(g))
#define CPC        asm volatile("cp.async.commit_group;")
#define CPW(n)     asm volatile("cp.async.wait_group %0;" :: "n"(n))

#define LDSM4(r0, r1, r2, r3, addr) asm volatile( \
    "ldmatrix.sync.aligned.m8n8.x4.shared.b16 {%0,%1,%2,%3}, [%4];" \
    : "=r"(r0), "=r"(r1), "=r"(r2), "=r"(r3) : "r"(addr))

#define MMA_F16(c, a0,a1,a2,a3, b0,b1) asm volatile( \
    "mma.sync.aligned.m16n8k16.row.col.f32.f16.f16.f32 " \
    "{%0,%1,%2,%3},{%4,%5,%6,%7},{%8,%9},{%0,%1,%2,%3};" \
    : "+f"((c)[0]), "+f"((c)[1]), "+f"((c)[2]), "+f"((c)[3]) \
    : "r"(a0), "r"(a1), "r"(a2), "r"(a3), "r"(b0), "r"(b1))

// pack two floats -> half2 ({lo=x0, hi=x1}) then 2^x elementwise
#define EXP2_PACK(dst, x0, x1) do { \
    u32 _p; \
    asm("cvt.rn.f16x2.f32 %0, %1, %2;" : "=r"(_p) : "f"(x1), "f"(x0)); \
    asm("ex2.approx.f16x2 %0, %0;" : "+r"(_p)); \
    (dst) = _p; \
} while (0)

#define ZERO_C3(c, MT) { _Pragma("unroll") for (int m = 0; m < MT; ++m) \
    _Pragma("unroll") for (int n = 0; n < 4; ++n) \
    _Pragma("unroll") for (int r = 0; r < 4; ++r) (c)[m][n][r] = 0.f; }

#define ZERO_C2(c, NT) { _Pragma("unroll") for (int n = 0; n < NT; ++n) \
    _Pragma("unroll") for (int r = 0; r < 4; ++r) (c)[n][r] = 0.f; }

// ============================================================================
// fp16 GEMM mainloop: C[128x128] = A[128x1024] @ B[128x1024]^T.
// k=64 stages (A 16KB + B 16KB), 128B rows, swizzle chunk ^= row&7.
// 3-stage cp.async, ldmatrix consumers, 8 warps 2x4.
// ============================================================================
#define GSTG 32768
__device__ __forceinline__ void gemm16_1024(
    const __half* __restrict__ A, const __half* __restrict__ Bm,
    char* dsm, u32 sb, float (&c)[4][4][4])
{
    const int tid = threadIdx.x, lane = tid & 31, wid = tid >> 5;
    const int wm = wid >> 2, wn = wid & 3;
    const int li = lane & 7, mi = lane >> 3;

    u32 sA[4], sB[4];
    const __half* gA[4];
    const __half* gB[4];
    #pragma unroll
    for (int p = 0; p < 4; ++p) {
        int id = tid + p * 256;
        int row = id >> 3, cc = id & 7;
        u32 sw = (u32)(row * 128 + ((cc ^ (row & 7)) << 4));
        sA[p] = sb + sw;
        gA[p] = A + (size_t)row * 1024 + cc * 8;
        sB[p] = sb + 16384 + sw;
        gB[p] = Bm + (size_t)row * 1024 + cc * 8;
    }
    auto load = [&](int s) {
        u32 off = (u32)((s % 3) * GSTG);
        int k0 = s << 6;
        #pragma unroll
        for (int p = 0; p < 4; ++p) CP16(sA[p] + off, gA[p] + k0);
        #pragma unroll
        for (int p = 0; p < 4; ++p) CP16(sB[p] + off, gB[p] + k0);
        CPC;
    };
    load(0); load(1);

    const u32 bfrag = (u32)(16384 + wn * 4096 + li * 128 + ((mi ^ li) << 4));
    const u32 aRow0 = (u32)((wm * 64 + ((mi & 1) << 3) + li) * 128);

    for (int ch = 0; ch < 16; ++ch) {
        CPW(1);
        __syncthreads();
        if (ch + 2 < 16) load(ch + 2); else CPC;
        u32 st = sb + (u32)((ch % 3) * GSTG);

        #pragma unroll
        for (int half = 0; half < 2; ++half) {
            u32 hx = (u32)(half << 6);
            u32 bb[4][4];
            #pragma unroll
            for (int nt = 0; nt < 4; ++nt)
                LDSM4(bb[nt][0], bb[nt][1], bb[nt][2], bb[nt][3],
                      (st + bfrag + nt * 1024) ^ hx);
            #pragma unroll
            for (int mt = 0; mt < 4; ++mt) {
                u32 aadr = st + aRow0 + mt * 2048;
                #pragma unroll
                for (int kt2 = 0; kt2 < 2; ++kt2) {
                    int kt = half * 2 + kt2;
                    u32 x = (u32)(((((kt << 1) | (mi >> 1))) ^ li) << 4);
                    u32 a0, a1, a2, a3;
                    LDSM4(a0, a1, a2, a3, aadr + x);
                    #pragma unroll
                    for (int nt = 0; nt < 4; ++nt)
                        MMA_F16(c[mt][nt], a0, a1, a2, a3,
                                bb[nt][kt2 * 2], bb[nt][kt2 * 2 + 1]);
                }
            }
        }
    }
}

// ============================================================================
// Prep kernels
// ============================================================================
__global__ __launch_bounds__(256) void k_xh(const float* __restrict__ x)
{
    size_t base = ((size_t)blockIdx.x * 256 + threadIdx.x) * 8;
    float4 v0 = *(const float4*)(x + base);
    float4 v1 = *(const float4*)(x + base + 4);
    __half2 h0 = __floats2half2_rn(v0.x, v0.y);
    __half2 h1 = __floats2half2_rn(v0.z, v0.w);
    __half2 h2 = __floats2half2_rn(v1.x, v1.y);
    __half2 h3 = __floats2half2_rn(v1.z, v1.w);
    *(uint4*)(g_xh + base) = make_uint4(*(u32*)&h0, *(u32*)&h1, *(u32*)&h2, *(u32*)&h3);
}

__global__ __launch_bounds__(256) void k_wqh(const float* __restrict__ w)
{
    __shared__ float tile[32][33];
    int bx = blockIdx.x * 32, by = blockIdx.y * 32;
    int tx = threadIdx.x, ty = threadIdx.y;
    float sc = (bx < 1024) ? SCALE_ * LOG2E_ : 1.0f;
    #pragma unroll
    for (int i = 0; i < 32; i += 8)
        tile[ty + i][tx] = w[(size_t)(by + ty + i) * 3072 + bx + tx];
    __syncthreads();
    #pragma unroll
    for (int i = 0; i < 32; i += 8)
        g_wqh[(size_t)(bx + ty + i) * 1024 + by + tx] = __float2half(tile[tx][ty + i] * sc);
}

__global__ __launch_bounds__(256) void k_woutT(const float* __restrict__ w)
{
    __shared__ float tile[32][33];
    int bx = blockIdx.x * 32, by = blockIdx.y * 32;
    int tx = threadIdx.x, ty = threadIdx.y;
    #pragma unroll
    for (int i = 0; i < 32; i += 8)
        tile[ty + i][tx] = w[(size_t)(by + ty + i) * D_ + bx + tx];
    __syncthreads();
    #pragma unroll
    for (int i = 0; i < 32; i += 8)
        g_woutTh[(size_t)(bx + ty + i) * D_ + by + tx] = __float2half(tile[tx][ty + i]);
}

// ============================================================================
// Kernel 1: QKV projection (fp16 1x). q/k -> [bh][s][dh]; V -> g_vTh transposed.
// ============================================================================
__global__ __launch_bounds__(256, 2) void k_qkv(const float* __restrict__ bias)
{
    extern __shared__ __align__(16) char dsm[];
    u32 sb = smem_u32(dsm);
    const int row0 = blockIdx.y * 128, col0 = blockIdx.x * 128;

    float c[4][4][4]; ZERO_C3(c, 4);
    gemm16_1024(g_xh + (size_t)row0 * 1024, g_wqh + (size_t)col0 * 1024, dsm, sb, c);

    const int lane = threadIdx.x & 31, wid = threadIdx.x >> 5;
    const int wm = wid >> 2, wn = wid & 3, g = lane >> 2, t = lane & 3;
    const int three = col0 >> 10;
    const float bsc = (three == 0) ? SCALE_ * LOG2E_ : 1.0f;
    #pragma unroll
    for (int nt = 0; nt < 4; ++nt) {
        int gcol = col0 + wn * 32 + nt * 8 + t * 2;
        float b0 = __ldg(bias + gcol) * bsc, b1 = __ldg(bias + gcol + 1) * bsc;
        int h = (gcol >> 6) & 15, dh = gcol & 63;
        #pragma unroll
        for (int mt = 0; mt < 4; ++mt)
            #pragma unroll
            for (int hh = 0; hh < 2; ++hh) {
                int gm = row0 + wm * 64 + mt * 16 + hh * 8 + g;
                int b = gm >> 11, s = gm & 2047;
                float v0 = c[mt][nt][hh * 2] + b0, v1 = c[mt][nt][hh * 2 + 1] + b1;
                if (three == 2) {
                    size_t vb = ((size_t)(b * 16 + h) * 64 + dh) * S_ + s;
                    g_vTh[vb]      = __float2half(v0);
                    g_vTh[vb + S_] = __float2half(v1);
                } else {
                    __half* dst = (three == 0) ? g_qh : g_kh;
                    size_t base = ((size_t)(b * 16 + h) * S_ + s) * 64 + dh;
                    __half2 hv = __floats2half2_rn(v0, v1);
                    *(u32*)(dst + base) = *(u32*)&hv;
                }
            }
    }
}

// ============================================================================
// Kernel 2: fused flash attention. Scores in log2 domain; ex2.approx.f16x2;
// row sums via ones-MMA (exact fp32).
// ============================================================================
#define ATQ   16384
#define ATSTG 16384
__global__ __launch_bounds__(256, 2) void k_attn()
{
    extern __shared__ __align__(16) char dsm[];
    u32 sb = smem_u32(dsm);
    const int tid = threadIdx.x, lane = tid & 31, wid = tid >> 5;
    const int g = lane >> 2, t = lane & 3;
    const int li = lane & 7, mi = lane >> 3;
    const int bh = blockIdx.y, row0 = blockIdx.x * 128;

    // Q producer (group 0)
    {
        const __half* qg = g_qh + ((size_t)bh * S_ + row0) * 64;
        #pragma unroll
        for (int p = 0; p < 4; ++p) {
            int id = tid + p * 256;
            int row = id >> 3, cc = id & 7;
            u32 off = (u32)(row * 128 + ((cc ^ (row & 7)) << 4));
            CP16(sb + off, qg + (size_t)row * 64 + cc * 8);
        }
        CPC;
    }

    // KV producers
    u32 kOff[2], vOff[2];
    const __half* kG[2];
    const __half* vG[2];
    #pragma unroll
    for (int p = 0; p < 2; ++p) {
        int id = tid + p * 256;
        int row = id >> 3, cc = id & 7;
        u32 sw = (u32)(row * 128 + ((cc ^ (row & 7)) << 4));
        kOff[p] = sw;
        kG[p] = g_kh + ((size_t)bh * S_ + row) * 64 + cc * 8;
        vOff[p] = 8192 + sw;
        vG[p] = g_vTh + ((size_t)bh * 64 + row) * S_ + cc * 8;
    }
    auto loadKV = [&](int it) {
        u32 so = sb + ATQ + (u32)((it & 3) * ATSTG);
        int kv0 = it * 64;
        #pragma unroll
        for (int p = 0; p < 2; ++p) CP16(so + kOff[p], kG[p] + (size_t)kv0 * 64);
        #pragma unroll
        for (int p = 0; p < 2; ++p) CP16(so + vOff[p], vG[p] + kv0);
        CPC;
    };
    loadKV(0); loadKV(1); loadKV(2);

    // Q fragments -> registers
    CPW(3);
    __syncthreads();
    u32 qf[4][4];
    {
        u32 qBase = sb + (u32)((wid * 16 + ((mi & 1) << 3) + li) * 128);
        #pragma unroll
        for (int kt = 0; kt < 4; ++kt) {
            u32 x = (u32)(((((kt << 1) | (mi >> 1))) ^ li) << 4);
            LDSM4(qf[kt][0], qf[kt][1], qf[kt][2], qf[kt][3], qBase + x);
        }
    }

    const u32 fragBase = (u32)(li * 128 + ((mi ^ li) << 4));
    const u32 ONE2 = 0x3C003C00u;   // half2(1, 1)

    float co[8][4]; ZERO_C2(co, 8);
    float cls[4];
    #pragma unroll
    for (int r = 0; r < 4; ++r) cls[r] = 0.f;

    for (int it = 0; it < 32; ++it) {
        CPW(2);
        __syncthreads();
        if (it + 3 < 32) loadKV(it + 3); else CPC;
        u32 stK = sb + ATQ + (u32)((it & 3) * ATSTG);
        u32 stV = stK + 8192;

        // S(log2) = Q K^T
        float cs[8][4]; ZERO_C2(cs, 8);
        #pragma unroll
        for (int nt = 0; nt < 8; ++nt) {
            u32 k0, k1, k2, k3, k4, k5, k6, k7;
            u32 adr = stK + fragBase + nt * 1024;
            LDSM4(k0, k1, k2, k3, adr);
            LDSM4(k4, k5, k6, k7, adr ^ 64);
            MMA_F16(cs[nt], qf[0][0], qf[0][1], qf[0][2], qf[0][3], k0, k1);
            MMA_F16(cs[nt], qf[1][0], qf[1][1], qf[1][2], qf[1][3], k2, k3);
            MMA_F16(cs[nt], qf[2][0], qf[2][1], qf[2][2], qf[2][3], k4, k5);
            MMA_F16(cs[nt], qf[3][0], qf[3][1], qf[3][2], qf[3][3], k6, k7);
        }

        // P = 2^S directly in fp16x2; pack into PV A-fragments
        u32 ap[4][4];
        #pragma unroll
        for (int nt = 0; nt < 8; ++nt) {
            u32 p01, p23;
            EXP2_PACK(p01, cs[nt][0], cs[nt][1]);
            EXP2_PACK(p23, cs[nt][2], cs[nt][3]);
            ap[nt >> 1][(nt & 1) * 2 + 0] = p01;
            ap[nt >> 1][(nt & 1) * 2 + 1] = p23;
        }

        // row sums: cls += P @ ones (exact fp32 accumulate)
        #pragma unroll
        for (int kt = 0; kt < 4; ++kt)
            MMA_F16(cls, ap[kt][0], ap[kt][1], ap[kt][2], ap[kt][3], ONE2, ONE2);

        // O += P V
        #pragma unroll
        for (int nt = 0; nt < 8; ++nt) {
            u32 v0, v1, v2, v3, v4, v5, v6, v7;
            u32 adr = stV + fragBase + nt * 1024;
            LDSM4(v0, v1, v2, v3, adr);
            LDSM4(v4, v5, v6, v7, adr ^ 64);
            MMA_F16(co[nt], ap[0][0], ap[0][1], ap[0][2], ap[0][3], v0, v1);
            MMA_F16(co[nt], ap[1][0], ap[1][1], ap[1][2], ap[1][3], v2, v3);
            MMA_F16(co[nt], ap[2][0], ap[2][1], ap[2][2], ap[2][3], v4, v5);
            MMA_F16(co[nt], ap[3][0], ap[3][1], ap[3][2], ap[3][3], v6, v7);
        }
    }

    // normalize and write (cls[0]/cls[2] already hold this thread's row sums)
    float inv0 = 1.0f / cls[0], inv1 = 1.0f / cls[2];

    const int b = bh >> 4, h = bh & 15;
    int r0 = row0 + wid * 16 + g;
    __half* o0 = g_aoh + ((size_t)b * S_ + r0) * D_ + h * 64;
    __half* o1 = o0 + (size_t)8 * D_;
    #pragma unroll
    for (int nt = 0; nt < 8; ++nt) {
        int dh = nt * 8 + t * 2;
        __half2 w0 = __floats2half2_rn(co[nt][0] * inv0, co[nt][1] * inv0);
        __half2 w1 = __floats2half2_rn(co[nt][2] * inv1, co[nt][3] * inv1);
        *(u32*)(o0 + dh) = *(u32*)&w0;
        *(u32*)(o1 + dh) = *(u32*)&w1;
    }
}

// ============================================================================
// Kernel 3: output projection (fp16 1x)
// ============================================================================
__global__ __launch_bounds__(256, 2) void k_out(
    const float* __restrict__ bias, float* __restrict__ out)
{
    extern __shared__ __align__(16) char dsm[];
    u32 sb = smem_u32(dsm);
    const int row0 = blockIdx.y * 128, col0 = blockIdx.x * 128;

    float c[4][4][4]; ZERO_C3(c, 4);
    gemm16_1024(g_aoh + (size_t)row0 * D_, g_woutTh + (size_t)col0 * D_, dsm, sb, c);

    const int lane = threadIdx.x & 31, wid = threadIdx.x >> 5;
    const int wm = wid >> 2, wn = wid & 3, g = lane >> 2, t = lane & 3;
    #pragma unroll
    for (int nt = 0; nt < 4; ++nt) {
        int gcol = col0 + wn * 32 + nt * 8 + t * 2;
        float b0 = __ldg(bias + gcol), b1 = __ldg(bias + gcol + 1);
        #pragma unroll
        for (int mt = 0; mt < 4; ++mt)
            #pragma unroll
            for (int hh = 0; hh < 2; ++hh) {
                int gm = row0 + wm * 64 + mt * 16 + hh * 8 + g;
                *(float2*)(out + (size_t)gm * D_ + gcol) =
                    make_float2(c[mt][nt][hh * 2] + b0, c[mt][nt][hh * 2 + 1] + b1);
            }
    }
}

// ---------------------------------------------------------------------------
#define DYN_G16 (3 * GSTG)          // 98304
#define DYN_ATT (ATQ + 4 * ATSTG)   // 81920

extern "C" void kernel_launch(void* const* d_in, const int* in_sizes, int n_in,
                              void* d_out, int out_size)
{
    (void)in_sizes; (void)n_in; (void)out_size;
    const float* x     = (const float*)d_in[0];
    const float* w_qkv = (const float*)d_in[1];
    const float* b_qkv = (const float*)d_in[2];
    const float* w_out = (const float*)d_in[3];
    const float* b_out = (const float*)d_in[4];
    float* out = (float*)d_out;

    cudaFuncSetAttribute(k_qkv,  cudaFuncAttributeMaxDynamicSharedMemorySize, DYN_G16);
    cudaFuncSetAttribute(k_attn, cudaFuncAttributeMaxDynamicSharedMemorySize, DYN_ATT);
    cudaFuncSetAttribute(k_out,  cudaFuncAttributeMaxDynamicSharedMemorySize, DYN_G16);

    k_xh<<<4096, 256>>>(x);
    k_wqh<<<dim3(96, 32), dim3(32, 8)>>>(w_qkv);
    k_woutT<<<dim3(32, 32), dim3(32, 8)>>>(w_out);

    k_qkv<<<dim3(24, 64), 256, DYN_G16>>>(b_qkv);
    k_attn<<<dim3(16, 64), 256, DYN_ATT>>>();
    k_out<<<dim3(8, 64), 256, DYN_G16>>>(b_out, out);
}